// round 1
// baseline (speedup 1.0000x reference)
#include <cuda_runtime.h>
#include <math.h>

#define TREE_TOTAL 2047
#define NG 64
#define NN (NG * TREE_TOTAL)      // 131008
#define NE (2 * NN)               // 262016
#define HD 256
#define HALF 128
#define NL 4
#define BN_EPS 1e-5f
#define LN_EPS 1e-5f

// ---------------- scratch (no allocation allowed) ----------------
__device__ float  g_h  [(size_t)NN * HD];
__device__ float  g_agg[(size_t)NN * HD];
__device__ float  g_y1 [(size_t)NN * HD];
__device__ float  g_y2 [(size_t)NN * HD];
__device__ float  g_root[NG * HD];
__device__ double g_sum [HD];     // zero-init; k_makescale re-zeroes after use
__device__ double g_sqsum[HD];
__device__ float  g_scale[HD];
__device__ float  g_shift[HD];

// ---------------- embedding: h = concat(emb_node[x0], emb_label[x1]) ----------------
__global__ void k_embed(const int* __restrict__ x,
                        const float* __restrict__ en,
                        const float* __restrict__ el) {
    int idx = blockIdx.x * blockDim.x + threadIdx.x;   // NN*64 threads, 1 float4 each
    if (idx >= NN * 64) return;
    int n = idx >> 6, q = idx & 63;
    float4 v;
    if (q < 32) {
        int e = x[2 * n];
        v = ((const float4*)(en + (size_t)e * HALF))[q];
    } else {
        int e = x[2 * n + 1];
        v = ((const float4*)(el + (size_t)e * HALF))[q - 32];
    }
    ((float4*)(g_h + (size_t)n * HD))[q] = v;
}

// ---------------- zero a float buffer (float4 granularity) ----------------
__global__ void k_zero(float4* __restrict__ p, int n4) {
    int i = blockIdx.x * blockDim.x + threadIdx.x;
    if (i < n4) p[i] = make_float4(0.f, 0.f, 0.f, 0.f);
}

// ---------------- edge scatter: agg[dst] += h[src] * w ----------------
__global__ void k_scatter(const int* __restrict__ src, const int* __restrict__ dst,
                          const float* __restrict__ w) {
    int idx = blockIdx.x * blockDim.x + threadIdx.x;   // NE*64 threads
    if (idx >= NE * 64) return;
    int e = idx >> 6, q = idx & 63;
    int s = src[e], d = dst[e];
    float ww = w[e];
    float4 v = ((const float4*)(g_h + (size_t)s * HD))[q];
    float* a = g_agg + (size_t)d * HD + q * 4;
    atomicAdd(a + 0, v.x * ww);
    atomicAdd(a + 1, v.y * ww);
    atomicAdd(a + 2, v.z * ww);
    atomicAdd(a + 3, v.w * ww);
}

// ---------------- last layer: per-graph sum of all node features ----------------
__global__ void k_rootsum() {
    int g = blockIdx.x;          // 64 graphs
    int c = blockIdx.y;          // 8 row chunks of 256
    int t = threadIdx.x;         // column
    int r0 = c * 256;
    int r1 = r0 + 256; if (r1 > TREE_TOTAL) r1 = TREE_TOTAL;
    float s = 0.f;
    const float* base = g_h + ((size_t)g * TREE_TOTAL) * HD + t;
    for (int r = r0; r < r1; r++) s += base[(size_t)r * HD];
    atomicAdd(&g_root[g * HD + t], s);
}

// ---------------- column stats: sum / sumsq over rows ----------------
__global__ void k_colstats(const float* __restrict__ y) {
    int t = threadIdx.x;
    float s = 0.f, ss = 0.f;
    for (int r = blockIdx.x; r < NN; r += gridDim.x) {
        float v = y[(size_t)r * HD + t];
        s += v; ss += v * v;
    }
    atomicAdd(&g_sum[t], (double)s);
    atomicAdd(&g_sqsum[t], (double)ss);
}

// ---------------- BN -> per-column scale/shift; re-zero stats ----------------
__global__ void k_makescale(const float* __restrict__ gamma, const float* __restrict__ beta) {
    int t = threadIdx.x;
    double m = g_sum[t] / (double)NN;
    double v = g_sqsum[t] / (double)NN - m * m;
    if (v < 0.0) v = 0.0;
    double rs = 1.0 / sqrt(v + (double)BN_EPS);
    float sc = gamma[t] * (float)rs;
    g_scale[t] = sc;
    g_shift[t] = beta[t] - (float)m * sc;
    g_sum[t] = 0.0;
    g_sqsum[t] = 0.0;
}

// ---------------- SGEMM: C[N,256] = op(A)[N,256] @ W^T + bias ----------------
// MODE 0: a = A1 + A2 (h + agg)
// MODE 1: a = relu(A1 * g_scale[k] + g_shift[k])   (BN+ReLU fused on y1)
// MODE 2: a = A1 + (row % 2047 == 0 ? g_root[row/2047] : 0)
template <int MODE>
__global__ void __launch_bounds__(256)
k_gemm(const float* __restrict__ A1, const float* __restrict__ A2,
       const float* __restrict__ W, const float* __restrict__ bias,
       float* __restrict__ C) {
    __shared__ float As[8][128];
    __shared__ float Bs[8][128];
    int m0 = blockIdx.x * 128;
    int n0 = blockIdx.y * 128;
    int tid = threadIdx.x;
    int arow = tid >> 1;           // 0..127
    int aq = (tid & 1) * 4;        // 0 or 4
    int tx = tid & 15, ty = tid >> 4;

    float acc[8][8];
#pragma unroll
    for (int i = 0; i < 8; i++)
#pragma unroll
        for (int j = 0; j < 8; j++) acc[i][j] = 0.f;

    int grow = m0 + arow;
    bool rok = grow < NN;
    const float* rootrow = nullptr;
    if (MODE == 2) {
        if (rok && (grow % TREE_TOTAL) == 0)
            rootrow = g_root + (grow / TREE_TOTAL) * HD;
    }

    for (int k0 = 0; k0 < HD; k0 += 8) {
        float4 av = make_float4(0.f, 0.f, 0.f, 0.f);
        if (rok) {
            av = *(const float4*)(A1 + (size_t)grow * HD + k0 + aq);
            if (MODE == 0) {
                float4 b4 = *(const float4*)(A2 + (size_t)grow * HD + k0 + aq);
                av.x += b4.x; av.y += b4.y; av.z += b4.z; av.w += b4.w;
            } else if (MODE == 1) {
                int kk = k0 + aq;
                av.x = fmaxf(av.x * g_scale[kk + 0] + g_shift[kk + 0], 0.f);
                av.y = fmaxf(av.y * g_scale[kk + 1] + g_shift[kk + 1], 0.f);
                av.z = fmaxf(av.z * g_scale[kk + 2] + g_shift[kk + 2], 0.f);
                av.w = fmaxf(av.w * g_scale[kk + 3] + g_shift[kk + 3], 0.f);
            } else if (MODE == 2) {
                if (rootrow) {
                    av.x += rootrow[k0 + aq + 0];
                    av.y += rootrow[k0 + aq + 1];
                    av.z += rootrow[k0 + aq + 2];
                    av.w += rootrow[k0 + aq + 3];
                }
            }
        }
        As[aq + 0][arow] = av.x;
        As[aq + 1][arow] = av.y;
        As[aq + 2][arow] = av.z;
        As[aq + 3][arow] = av.w;

        float4 bv = *(const float4*)(W + (size_t)(n0 + arow) * HD + k0 + aq);
        Bs[aq + 0][arow] = bv.x;
        Bs[aq + 1][arow] = bv.y;
        Bs[aq + 2][arow] = bv.z;
        Bs[aq + 3][arow] = bv.w;

        __syncthreads();
#pragma unroll
        for (int k = 0; k < 8; k++) {
            float a[8], b[8];
            *(float4*)(a + 0) = *(const float4*)&As[k][ty * 8 + 0];
            *(float4*)(a + 4) = *(const float4*)&As[k][ty * 8 + 4];
            *(float4*)(b + 0) = *(const float4*)&Bs[k][tx * 8 + 0];
            *(float4*)(b + 4) = *(const float4*)&Bs[k][tx * 8 + 4];
#pragma unroll
            for (int i = 0; i < 8; i++)
#pragma unroll
                for (int j = 0; j < 8; j++) acc[i][j] += a[i] * b[j];
        }
        __syncthreads();
    }

    float4 bb0 = *(const float4*)(bias + n0 + tx * 8 + 0);
    float4 bb1 = *(const float4*)(bias + n0 + tx * 8 + 4);
#pragma unroll
    for (int i = 0; i < 8; i++) {
        int r = m0 + ty * 8 + i;
        if (r < NN) {
            float4 v0 = make_float4(acc[i][0] + bb0.x, acc[i][1] + bb0.y,
                                    acc[i][2] + bb0.z, acc[i][3] + bb0.w);
            float4 v1 = make_float4(acc[i][4] + bb1.x, acc[i][5] + bb1.y,
                                    acc[i][6] + bb1.z, acc[i][7] + bb1.w);
            *(float4*)(C + (size_t)r * HD + n0 + tx * 8 + 0) = v0;
            *(float4*)(C + (size_t)r * HD + n0 + tx * 8 + 4) = v1;
        }
    }
}

// ---------------- residual + LayerNorm: h = LN(h + relu(y2*s+t)) ----------------
__global__ void k_resln(const float* __restrict__ y2,
                        const float* __restrict__ lng, const float* __restrict__ lnb) {
    int r = blockIdx.x;
    int t = threadIdx.x;
    size_t idx = (size_t)r * HD + t;
    float u = g_h[idx] + fmaxf(y2[idx] * g_scale[t] + g_shift[t], 0.f);

    float s = u, ss = u * u;
#pragma unroll
    for (int o = 16; o > 0; o >>= 1) {
        s  += __shfl_down_sync(0xffffffffu, s, o);
        ss += __shfl_down_sync(0xffffffffu, ss, o);
    }
    __shared__ float sh_s[8], sh_ss[8];
    int w = t >> 5, l = t & 31;
    if (l == 0) { sh_s[w] = s; sh_ss[w] = ss; }
    __syncthreads();
    float ts = 0.f, tss = 0.f;
#pragma unroll
    for (int i = 0; i < 8; i++) { ts += sh_s[i]; tss += sh_ss[i]; }

    float mean = ts * (1.f / HD);
    float var = tss * (1.f / HD) - mean * mean;
    if (var < 0.f) var = 0.f;
    float rs = rsqrtf(var + LN_EPS);
    g_h[idx] = lng[t] * (u - mean) * rs + lnb[t];
}

// ---------------- readout: out[g,o] = h[root_g] . Wout[o] ----------------
__global__ void k_out(const float* __restrict__ Wout, float* __restrict__ out) {
    int g = blockIdx.x;
    int w = threadIdx.x >> 5;   // output index 0..31
    int l = threadIdx.x & 31;
    const float* hr = g_h + (size_t)g * TREE_TOTAL * HD;
    const float* wr = Wout + (size_t)w * HD;
    float s = 0.f;
#pragma unroll
    for (int k = l; k < HD; k += 32) s += hr[k] * wr[k];
#pragma unroll
    for (int o = 16; o > 0; o >>= 1) s += __shfl_down_sync(0xffffffffu, s, o);
    if (l == 0) out[g * 32 + w] = s;
}

// ---------------- launch ----------------
extern "C" void kernel_launch(void* const* d_in, const int* in_sizes, int n_in,
                              void* d_out, int out_size) {
    const int*   x    = (const int*)d_in[0];
    const int*   esrc = (const int*)d_in[1];
    const int*   edst = (const int*)d_in[2];
    const float* ew   = (const float*)d_in[3];
    // d_in[4] batch, d_in[5] root_index: closed-form, unused
    const float* en   = (const float*)d_in[6];
    const float* el   = (const float*)d_in[7];
    const float* W1   = (const float*)d_in[8];
    const float* b1   = (const float*)d_in[9];
    const float* g1   = (const float*)d_in[10];
    const float* be1  = (const float*)d_in[11];
    const float* W2   = (const float*)d_in[12];
    const float* b2   = (const float*)d_in[13];
    const float* g2   = (const float*)d_in[14];
    const float* be2  = (const float*)d_in[15];
    const float* lng  = (const float*)d_in[16];
    const float* lnb  = (const float*)d_in[17];
    const float* Wout = (const float*)d_in[18];
    float* out = (float*)d_out;

    float *h, *agg, *y1, *y2, *root;
    cudaGetSymbolAddress((void**)&h,    g_h);
    cudaGetSymbolAddress((void**)&agg,  g_agg);
    cudaGetSymbolAddress((void**)&y1,   g_y1);
    cudaGetSymbolAddress((void**)&y2,   g_y2);
    cudaGetSymbolAddress((void**)&root, g_root);

    dim3 ggrid(1024, 2);

    k_embed<<<(NN * 64) / 256, 256>>>(x, en, el);

    for (int i = 0; i < NL; i++) {
        const float* W1i = W1 + (size_t)i * HD * HD;
        const float* W2i = W2 + (size_t)i * HD * HD;
        const float* b1i = b1 + i * HD;
        const float* b2i = b2 + i * HD;
        const float* g1i = g1 + i * HD;
        const float* g2i = g2 + i * HD;
        const float* be1i = be1 + i * HD;
        const float* be2i = be2 + i * HD;
        const float* lngi = lng + i * HD;
        const float* lnbi = lnb + i * HD;

        if (i < NL - 1) {
            k_zero<<<(NN * 64) / 256, 256>>>((float4*)agg, NN * 64);
            k_scatter<<<(NE * 64) / 256, 256>>>(esrc, edst, ew);
            k_gemm<0><<<ggrid, 256>>>(h, agg, W1i, b1i, y1);
        } else {
            k_zero<<<64, 256>>>((float4*)root, NG * HD / 4);
            k_rootsum<<<dim3(NG, 8), 256>>>();
            k_gemm<2><<<ggrid, 256>>>(h, nullptr, W1i, b1i, y1);
        }
        k_colstats<<<512, 256>>>(y1);
        k_makescale<<<1, 256>>>(g1i, be1i);
        k_gemm<1><<<ggrid, 256>>>(y1, nullptr, W2i, b2i, y2);
        k_colstats<<<512, 256>>>(y2);
        k_makescale<<<1, 256>>>(g2i, be2i);
        k_resln<<<NN, 256>>>(y2, lngi, lnbi);
    }

    k_out<<<NG, 1024>>>(Wout, out);
}

// round 3
// speedup vs baseline: 1.0679x; 1.0679x over previous
#include <cuda_runtime.h>
#include <math.h>
#include <stdint.h>

#define TREE_TOTAL 2047
#define NG 64
#define NN (NG * TREE_TOTAL)      // 131008
#define NE (2 * NN)               // 262016
#define HD 256
#define HALF 128
#define NL 4
#define BN_EPS 1e-5f
#define LN_EPS 1e-5f

// ---------------- scratch (no allocation allowed) ----------------
__device__ float  g_h  [(size_t)NN * HD];
__device__ float  g_agg[(size_t)NN * HD];
__device__ float  g_y1 [(size_t)NN * HD];
__device__ float  g_y2 [(size_t)NN * HD];
__device__ float  g_root[NG * HD];
__device__ double g_sum [HD];     // zero-init; k_makescale re-zeroes after use
__device__ double g_sqsum[HD];
__device__ float  g_scale[HD];
__device__ float  g_shift[HD];

__device__ __forceinline__ uint32_t f2tf32(float x) {
    uint32_t r;
    asm("cvt.rna.tf32.f32 %0, %1;" : "=r"(r) : "f"(x));
    return r;
}

// ---------------- embedding: h = concat(emb_node[x0], emb_label[x1]) ----------------
__global__ void k_embed(const int* __restrict__ x,
                        const float* __restrict__ en,
                        const float* __restrict__ el) {
    int idx = blockIdx.x * blockDim.x + threadIdx.x;
    if (idx >= NN * 64) return;
    int n = idx >> 6, q = idx & 63;
    float4 v;
    if (q < 32) {
        int e = x[2 * n];
        v = ((const float4*)(en + (size_t)e * HALF))[q];
    } else {
        int e = x[2 * n + 1];
        v = ((const float4*)(el + (size_t)e * HALF))[q - 32];
    }
    ((float4*)(g_h + (size_t)n * HD))[q] = v;
}

// ---------------- zero a float buffer ----------------
__global__ void k_zero(float4* __restrict__ p, int n4) {
    int i = blockIdx.x * blockDim.x + threadIdx.x;
    if (i < n4) p[i] = make_float4(0.f, 0.f, 0.f, 0.f);
}

// ---------------- edge scatter: agg[dst] += h[src] * w ----------------
__global__ void k_scatter(const int* __restrict__ src, const int* __restrict__ dst,
                          const float* __restrict__ w) {
    int idx = blockIdx.x * blockDim.x + threadIdx.x;
    if (idx >= NE * 64) return;
    int e = idx >> 6, q = idx & 63;
    int s = src[e], d = dst[e];
    float ww = w[e];
    float4 v = ((const float4*)(g_h + (size_t)s * HD))[q];
    float* a = g_agg + (size_t)d * HD + q * 4;
    atomicAdd(a + 0, v.x * ww);
    atomicAdd(a + 1, v.y * ww);
    atomicAdd(a + 2, v.z * ww);
    atomicAdd(a + 3, v.w * ww);
}

// ---------------- last layer: per-graph sum of all node features ----------------
__global__ void k_rootsum() {
    int g = blockIdx.x;
    int c = blockIdx.y;
    int t = threadIdx.x;
    int r0 = c * 256;
    int r1 = r0 + 256; if (r1 > TREE_TOTAL) r1 = TREE_TOTAL;
    float s = 0.f;
    const float* base = g_h + ((size_t)g * TREE_TOTAL) * HD + t;
    for (int r = r0; r < r1; r++) s += base[(size_t)r * HD];
    atomicAdd(&g_root[g * HD + t], s);
}

// ---------------- BN -> per-column scale/shift; re-zero stats ----------------
__global__ void k_makescale(const float* __restrict__ gamma, const float* __restrict__ beta) {
    int t = threadIdx.x;
    double m = g_sum[t] / (double)NN;
    double v = g_sqsum[t] / (double)NN - m * m;
    if (v < 0.0) v = 0.0;
    double rs = 1.0 / sqrt(v + (double)BN_EPS);
    float sc = gamma[t] * (float)rs;
    g_scale[t] = sc;
    g_shift[t] = beta[t] - (float)m * sc;
    g_sum[t] = 0.0;
    g_sqsum[t] = 0.0;
}

// ============================================================================
// TF32x3 tensor-core GEMM (error-compensated, fp32-class accuracy):
//   C[NN,256] = op(A)[NN,256] @ W^T + bias
//   a = a_hi + a_lo, b = b_hi + b_lo; C ~= ah*bh + ah*bl + al*bh
// Fused column sum/sumsq stats into epilogue (for following BatchNorm).
// MODE 0: a = A1 + A2
// MODE 1: a = relu(A1 * g_scale[k] + g_shift[k])
// MODE 2: a = A1 + (row % 2047 == 0 ? g_root[row/2047] : 0)
// Block tile 128x128, BK=16, 8 warps (2 along M x 4 along N), warp tile 64x32.
// ============================================================================
#define LDS_P 130   // smem leading stride (u32): conflict-free for this pattern

template <int MODE>
__global__ void __launch_bounds__(256, 2)
k_gemm_tc(const float* __restrict__ A1, const float* __restrict__ A2,
          const float* __restrict__ W, const float* __restrict__ bias,
          float* __restrict__ C) {
    __shared__ uint32_t AsH[16 * LDS_P];
    __shared__ uint32_t AsL[16 * LDS_P];
    __shared__ uint32_t BsH[16 * LDS_P];
    __shared__ uint32_t BsL[16 * LDS_P];

    const int m0 = blockIdx.x * 128;
    const int n0 = blockIdx.y * 128;
    const int tid = threadIdx.x;
    const int lane = tid & 31;
    const int warp = tid >> 5;
    const int wm = warp & 1;        // 0..1 -> 64-row slab
    const int wn = warp >> 1;       // 0..3 -> 32-col slab

    const int lrow = tid >> 1;              // 0..127 (A row / B n within tile)
    const int kqb  = (tid & 1) * 2;         // base float4-index in k (0 or 2)

    const int grow = m0 + lrow;
    const bool rok = grow < NN;
    const float* rootrow = nullptr;
    if (MODE == 2 && rok && (grow % TREE_TOTAL) == 0)
        rootrow = g_root + (grow / TREE_TOTAL) * HD;

    float acc[4][4][4];
#pragma unroll
    for (int i = 0; i < 4; i++)
#pragma unroll
        for (int j = 0; j < 4; j++)
#pragma unroll
            for (int q = 0; q < 4; q++) acc[i][j][q] = 0.f;

    float4 ra[2], rb[2];

    auto loadA = [&](int k0) {
#pragma unroll
        for (int p = 0; p < 2; p++) {
            int kg = k0 + (kqb + p) * 4;
            float4 v = make_float4(0.f, 0.f, 0.f, 0.f);
            if (rok) {
                v = *(const float4*)(A1 + (size_t)grow * HD + kg);
                if (MODE == 0) {
                    float4 w4 = *(const float4*)(A2 + (size_t)grow * HD + kg);
                    v.x += w4.x; v.y += w4.y; v.z += w4.z; v.w += w4.w;
                } else if (MODE == 1) {
                    v.x = fmaxf(v.x * g_scale[kg + 0] + g_shift[kg + 0], 0.f);
                    v.y = fmaxf(v.y * g_scale[kg + 1] + g_shift[kg + 1], 0.f);
                    v.z = fmaxf(v.z * g_scale[kg + 2] + g_shift[kg + 2], 0.f);
                    v.w = fmaxf(v.w * g_scale[kg + 3] + g_shift[kg + 3], 0.f);
                } else if (MODE == 2) {
                    if (rootrow) {
                        v.x += rootrow[kg + 0]; v.y += rootrow[kg + 1];
                        v.z += rootrow[kg + 2]; v.w += rootrow[kg + 3];
                    }
                }
            }
            ra[p] = v;
        }
    };
    auto loadB = [&](int k0) {
#pragma unroll
        for (int p = 0; p < 2; p++) {
            int kg = k0 + (kqb + p) * 4;
            rb[p] = *(const float4*)(W + (size_t)(n0 + lrow) * HD + kg);
        }
    };
    // split a float into (hi tf32, lo tf32) and store to smem arrays
    auto stsAB = [&]() {
#pragma unroll
        for (int p = 0; p < 2; p++) {
            int base = ((kqb + p) * 4) * LDS_P + lrow;
            const float av[4] = { ra[p].x, ra[p].y, ra[p].z, ra[p].w };
            const float bv[4] = { rb[p].x, rb[p].y, rb[p].z, rb[p].w };
#pragma unroll
            for (int q = 0; q < 4; q++) {
                uint32_t ah = f2tf32(av[q]);
                uint32_t al = f2tf32(av[q] - __uint_as_float(ah));
                uint32_t bh = f2tf32(bv[q]);
                uint32_t bl = f2tf32(bv[q] - __uint_as_float(bh));
                AsH[base + q * LDS_P] = ah;
                AsL[base + q * LDS_P] = al;
                BsH[base + q * LDS_P] = bh;
                BsL[base + q * LDS_P] = bl;
            }
        }
    };

    loadA(0); loadB(0);
    stsAB();
    __syncthreads();

    const int arow = wm * 64 + (lane >> 2);   // + mt*16 (+8)
    const int bn   = wn * 32 + (lane >> 2);   // + nt*8
    const int kl   = lane & 3;

    for (int k0 = 16; k0 <= HD; k0 += 16) {
        if (k0 < HD) { loadA(k0); loadB(k0); }

#pragma unroll
        for (int ks = 0; ks < 2; ks++) {
            const int kb = ks * 8 + kl;
            uint32_t bh[4][2], bl[4][2];
#pragma unroll
            for (int nt = 0; nt < 4; nt++) {
                int n = bn + nt * 8;
                bh[nt][0] = BsH[kb * LDS_P + n];
                bh[nt][1] = BsH[(kb + 4) * LDS_P + n];
                bl[nt][0] = BsL[kb * LDS_P + n];
                bl[nt][1] = BsL[(kb + 4) * LDS_P + n];
            }
#pragma unroll
            for (int mt = 0; mt < 4; mt++) {
                int r = arow + mt * 16;
                uint32_t ah[4], al[4];
                ah[0] = AsH[kb * LDS_P + r];
                ah[1] = AsH[kb * LDS_P + r + 8];
                ah[2] = AsH[(kb + 4) * LDS_P + r];
                ah[3] = AsH[(kb + 4) * LDS_P + r + 8];
                al[0] = AsL[kb * LDS_P + r];
                al[1] = AsL[kb * LDS_P + r + 8];
                al[2] = AsL[(kb + 4) * LDS_P + r];
                al[3] = AsL[(kb + 4) * LDS_P + r + 8];
#pragma unroll
                for (int nt = 0; nt < 4; nt++) {
#define MMA(Afrag, Bfrag)                                                     \
    asm volatile(                                                             \
        "mma.sync.aligned.m16n8k8.row.col.f32.tf32.tf32.f32 "                 \
        "{%0,%1,%2,%3}, {%4,%5,%6,%7}, {%8,%9}, {%0,%1,%2,%3};"               \
        : "+f"(acc[mt][nt][0]), "+f"(acc[mt][nt][1]),                         \
          "+f"(acc[mt][nt][2]), "+f"(acc[mt][nt][3])                          \
        : "r"(Afrag[0]), "r"(Afrag[1]), "r"(Afrag[2]), "r"(Afrag[3]),         \
          "r"(Bfrag[0]), "r"(Bfrag[1]))
                    MMA(al, bh[nt]);
                    MMA(ah, bl[nt]);
                    MMA(ah, bh[nt]);
#undef MMA
                }
            }
        }
        __syncthreads();
        if (k0 < HD) { stsAB(); __syncthreads(); }
    }

    // ---- epilogue: bias add, store, fused column sum/sumsq ----
#pragma unroll
    for (int nt = 0; nt < 4; nt++) {
        int c = n0 + wn * 32 + nt * 8 + (lane & 3) * 2;
        float bv0 = bias[c], bv1 = bias[c + 1];
        float s0 = 0.f, s1 = 0.f, q0 = 0.f, q1 = 0.f;
#pragma unroll
        for (int mt = 0; mt < 4; mt++) {
            int r = m0 + wm * 64 + mt * 16 + (lane >> 2);
#pragma unroll
            for (int hh = 0; hh < 2; hh++) {
                int rr = r + hh * 8;
                if (rr < NN) {
                    float v0 = acc[mt][nt][hh * 2 + 0] + bv0;
                    float v1 = acc[mt][nt][hh * 2 + 1] + bv1;
                    *(float2*)(C + (size_t)rr * HD + c) = make_float2(v0, v1);
                    s0 += v0; s1 += v1;
                    q0 += v0 * v0; q1 += v1 * v1;
                }
            }
        }
#pragma unroll
        for (int o = 4; o < 32; o <<= 1) {
            s0 += __shfl_xor_sync(0xffffffffu, s0, o);
            s1 += __shfl_xor_sync(0xffffffffu, s1, o);
            q0 += __shfl_xor_sync(0xffffffffu, q0, o);
            q1 += __shfl_xor_sync(0xffffffffu, q1, o);
        }
        if ((lane >> 2) == 0) {
            atomicAdd(&g_sum[c],     (double)s0);
            atomicAdd(&g_sum[c + 1], (double)s1);
            atomicAdd(&g_sqsum[c],     (double)q0);
            atomicAdd(&g_sqsum[c + 1], (double)q1);
        }
    }
}

// ---------------- residual + LayerNorm: h = LN(h + relu(y2*s+t)) ----------------
__global__ void k_resln(const float* __restrict__ y2,
                        const float* __restrict__ lng, const float* __restrict__ lnb) {
    int r = blockIdx.x;
    int t = threadIdx.x;
    size_t idx = (size_t)r * HD + t;
    float u = g_h[idx] + fmaxf(y2[idx] * g_scale[t] + g_shift[t], 0.f);

    float s = u, ss = u * u;
#pragma unroll
    for (int o = 16; o > 0; o >>= 1) {
        s  += __shfl_down_sync(0xffffffffu, s, o);
        ss += __shfl_down_sync(0xffffffffu, ss, o);
    }
    __shared__ float sh_s[8], sh_ss[8];
    int w = t >> 5, l = t & 31;
    if (l == 0) { sh_s[w] = s; sh_ss[w] = ss; }
    __syncthreads();
    float ts = 0.f, tss = 0.f;
#pragma unroll
    for (int i = 0; i < 8; i++) { ts += sh_s[i]; tss += sh_ss[i]; }

    float mean = ts * (1.f / HD);
    float var = tss * (1.f / HD) - mean * mean;
    if (var < 0.f) var = 0.f;
    float rs = rsqrtf(var + LN_EPS);
    g_h[idx] = lng[t] * (u - mean) * rs + lnb[t];
}

// ---------------- readout: out[g,o] = h[root_g] . Wout[o] ----------------
__global__ void k_out(const float* __restrict__ Wout, float* __restrict__ out) {
    int g = blockIdx.x;
    int w = threadIdx.x >> 5;
    int l = threadIdx.x & 31;
    const float* hr = g_h + (size_t)g * TREE_TOTAL * HD;
    const float* wr = Wout + (size_t)w * HD;
    float s = 0.f;
#pragma unroll
    for (int k = l; k < HD; k += 32) s += hr[k] * wr[k];
#pragma unroll
    for (int o = 16; o > 0; o >>= 1) s += __shfl_down_sync(0xffffffffu, s, o);
    if (l == 0) out[g * 32 + w] = s;
}

// ---------------- launch ----------------
extern "C" void kernel_launch(void* const* d_in, const int* in_sizes, int n_in,
                              void* d_out, int out_size) {
    const int*   x    = (const int*)d_in[0];
    const int*   esrc = (const int*)d_in[1];
    const int*   edst = (const int*)d_in[2];
    const float* ew   = (const float*)d_in[3];
    const float* en   = (const float*)d_in[6];
    const float* el   = (const float*)d_in[7];
    const float* W1   = (const float*)d_in[8];
    const float* b1   = (const float*)d_in[9];
    const float* g1   = (const float*)d_in[10];
    const float* be1  = (const float*)d_in[11];
    const float* W2   = (const float*)d_in[12];
    const float* b2   = (const float*)d_in[13];
    const float* g2   = (const float*)d_in[14];
    const float* be2  = (const float*)d_in[15];
    const float* lng  = (const float*)d_in[16];
    const float* lnb  = (const float*)d_in[17];
    const float* Wout = (const float*)d_in[18];
    float* out = (float*)d_out;

    float *h, *agg, *y1, *y2, *root;
    cudaGetSymbolAddress((void**)&h,    g_h);
    cudaGetSymbolAddress((void**)&agg,  g_agg);
    cudaGetSymbolAddress((void**)&y1,   g_y1);
    cudaGetSymbolAddress((void**)&y2,   g_y2);
    cudaGetSymbolAddress((void**)&root, g_root);

    dim3 ggrid(1024, 2);

    k_embed<<<(NN * 64) / 256, 256>>>(x, en, el);

    for (int i = 0; i < NL; i++) {
        const float* W1i = W1 + (size_t)i * HD * HD;
        const float* W2i = W2 + (size_t)i * HD * HD;
        const float* b1i = b1 + i * HD;
        const float* b2i = b2 + i * HD;
        const float* g1i = g1 + i * HD;
        const float* g2i = g2 + i * HD;
        const float* be1i = be1 + i * HD;
        const float* be2i = be2 + i * HD;
        const float* lngi = lng + i * HD;
        const float* lnbi = lnb + i * HD;

        if (i < NL - 1) {
            k_zero<<<(NN * 64) / 256, 256>>>((float4*)agg, NN * 64);
            k_scatter<<<(NE * 64) / 256, 256>>>(esrc, edst, ew);
            k_gemm_tc<0><<<ggrid, 256>>>(h, agg, W1i, b1i, y1);
        } else {
            k_zero<<<64, 256>>>((float4*)root, NG * HD / 4);
            k_rootsum<<<dim3(NG, 8), 256>>>();
            k_gemm_tc<2><<<ggrid, 256>>>(h, nullptr, W1i, b1i, y1);
        }
        k_makescale<<<1, 256>>>(g1i, be1i);
        k_gemm_tc<1><<<ggrid, 256>>>(y1, nullptr, W2i, b2i, y2);
        k_makescale<<<1, 256>>>(g2i, be2i);
        k_resln<<<NN, 256>>>(y2, lngi, lnbi);
    }

    k_out<<<NG, 1024>>>(Wout, out);
}

// round 5
// speedup vs baseline: 1.5130x; 1.4168x over previous
#include <cuda_runtime.h>
#include <math.h>
#include <stdint.h>

#define TREE_TOTAL 2047
#define NG 64
#define NN (NG * TREE_TOTAL)      // 131008
#define NE (2 * NN)               // 262016
#define HD 256
#define HALF 128
#define NL 4
#define BN_EPS 1e-5f
#define LN_EPS 1e-5f

// ---------------- scratch (no allocation allowed) ----------------
__device__ float  g_h  [(size_t)NN * HD];
__device__ float  g_agg[(size_t)NN * HD];
__device__ float  g_y1 [(size_t)NN * HD];
__device__ float  g_y2 [(size_t)NN * HD];
__device__ float  g_root[NG * HD];
__device__ double g_sum [HD];     // zero-init; k_makescale re-zeroes after use
__device__ double g_sqsum[HD];
__device__ float  g_scale[HD];
__device__ float  g_shift[HD];

// ---------------- embedding: h = concat(emb_node[x0], emb_label[x1]) ----------------
__global__ void k_embed(const int* __restrict__ x,
                        const float* __restrict__ en,
                        const float* __restrict__ el) {
    int idx = blockIdx.x * blockDim.x + threadIdx.x;
    if (idx >= NN * 64) return;
    int n = idx >> 6, q = idx & 63;
    float4 v;
    if (q < 32) {
        int e = x[2 * n];
        v = ((const float4*)(en + (size_t)e * HALF))[q];
    } else {
        int e = x[2 * n + 1];
        v = ((const float4*)(el + (size_t)e * HALF))[q - 32];
    }
    ((float4*)(g_h + (size_t)n * HD))[q] = v;
}

// ---------------- zero a float buffer ----------------
__global__ void k_zero(float4* __restrict__ p, int n4) {
    int i = blockIdx.x * blockDim.x + threadIdx.x;
    if (i < n4) p[i] = make_float4(0.f, 0.f, 0.f, 0.f);
}

// ---------------- edge scatter: agg[dst] += h[src] * w ----------------
__global__ void k_scatter(const int* __restrict__ src, const int* __restrict__ dst,
                          const float* __restrict__ w) {
    int idx = blockIdx.x * blockDim.x + threadIdx.x;
    if (idx >= NE * 64) return;
    int e = idx >> 6, q = idx & 63;
    int s = src[e], d = dst[e];
    float ww = w[e];
    float4 v = ((const float4*)(g_h + (size_t)s * HD))[q];
    float* a = g_agg + (size_t)d * HD + q * 4;
    atomicAdd(a + 0, v.x * ww);
    atomicAdd(a + 1, v.y * ww);
    atomicAdd(a + 2, v.z * ww);
    atomicAdd(a + 3, v.w * ww);
}

// ---------------- last layer: per-graph sum of all node features ----------------
__global__ void k_rootsum() {
    int g = blockIdx.x;
    int c = blockIdx.y;
    int t = threadIdx.x;
    int r0 = c * 256;
    int r1 = r0 + 256; if (r1 > TREE_TOTAL) r1 = TREE_TOTAL;
    float s = 0.f;
    const float* base = g_h + ((size_t)g * TREE_TOTAL) * HD + t;
    for (int r = r0; r < r1; r++) s += base[(size_t)r * HD];
    atomicAdd(&g_root[g * HD + t], s);
}

// ---------------- BN -> per-column scale/shift; re-zero stats ----------------
__global__ void k_makescale(const float* __restrict__ gamma, const float* __restrict__ beta) {
    int t = threadIdx.x;
    double m = g_sum[t] / (double)NN;
    double v = g_sqsum[t] / (double)NN - m * m;
    if (v < 0.0) v = 0.0;
    double rs = 1.0 / sqrt(v + (double)BN_EPS);
    float sc = gamma[t] * (float)rs;
    g_scale[t] = sc;
    g_shift[t] = beta[t] - (float)m * sc;
    g_sum[t] = 0.0;
    g_sqsum[t] = 0.0;
}

// ============================================================================
// BF16x3 tensor-core GEMM (error-compensated, ~fp32 accuracy):
//   a = ah + al (both bf16), b = bh + bl; C ~= ah*bh + ah*bl + al*bh
// mma.sync.aligned.m16n8k16.row.col.f32.bf16.bf16.f32
// Block tile 128x128, BK=16, 512 threads (16 warps, 4m x 4n), warp tile 32x32.
// Double-buffered smem, one __syncthreads per K-tile.
// Fused column sum/sumsq stats in epilogue (smem reduce -> 1 f64 atomic/col).
// MODE 0: a = A1 + A2
// MODE 1: a = relu(A1 * g_scale[k] + g_shift[k])
// MODE 2: a = A1 + (row % 2047 == 0 ? g_root[row/2047] : 0)
// ============================================================================
#define GP 136   // smem row stride (u32): conflict-free frag LDS

// split two floats (even k, odd k) into hi/lo bf16x2 packed words
__device__ __forceinline__ void split2(float e, float o, uint32_t& hi, uint32_t& lo) {
    uint32_t h;
    asm("cvt.rn.bf16x2.f32 %0, %1, %2;" : "=r"(h) : "f"(o), "f"(e));
    float ef = __uint_as_float(h << 16);
    float of = __uint_as_float(h & 0xffff0000u);
    float re = e - ef;
    float ro = o - of;
    uint32_t l;
    asm("cvt.rn.bf16x2.f32 %0, %1, %2;" : "=r"(l) : "f"(ro), "f"(re));
    hi = h; lo = l;
}

template <int MODE>
__global__ void __launch_bounds__(512, 1)
k_gemm_tc(const float* __restrict__ A1, const float* __restrict__ A2,
          const float* __restrict__ W, const float* __restrict__ bias,
          float* __restrict__ C) {
    // [stage][matrix: 0=Ah 1=Al 2=Bh 3=Bl][kp*GP + row]
    __shared__ uint32_t sm[2][4][8 * GP];
    __shared__ float s_sum[128], s_ss[128];

    const int m0 = blockIdx.x * 128;
    const int n0 = blockIdx.y * 128;
    const int tid = threadIdx.x;
    const int lane = tid & 31;
    const int warp = tid >> 5;
    const int wm = warp & 3;        // 32-row slab
    const int wn = warp >> 2;       // 32-col slab

    // loader mapping: one float4 of A and of B per K-tile
    const int lrow = tid >> 2;      // 0..127
    const int kq   = tid & 3;       // float4 index within 16-wide k
    const int grow = m0 + lrow;
    const bool rok = grow < NN;
    const float* rootrow = nullptr;
    if (MODE == 2 && rok && (grow % TREE_TOTAL) == 0)
        rootrow = g_root + (grow / TREE_TOTAL) * HD;

    if (tid < 128) { s_sum[tid] = 0.f; s_ss[tid] = 0.f; }

    float acc[2][4][4];
#pragma unroll
    for (int i = 0; i < 2; i++)
#pragma unroll
        for (int j = 0; j < 4; j++)
#pragma unroll
            for (int q = 0; q < 4; q++) acc[i][j][q] = 0.f;

    float4 va, vb;

    auto ldg = [&](int kt) {
        int kg = kt * 16 + kq * 4;
        vb = *(const float4*)(W + (size_t)(n0 + lrow) * HD + kg);
        if (rok) {
            va = *(const float4*)(A1 + (size_t)grow * HD + kg);
            if (MODE == 0) {
                float4 w4 = *(const float4*)(A2 + (size_t)grow * HD + kg);
                va.x += w4.x; va.y += w4.y; va.z += w4.z; va.w += w4.w;
            } else if (MODE == 1) {
                float4 sc = *(const float4*)(g_scale + kg);
                float4 sh = *(const float4*)(g_shift + kg);
                va.x = fmaxf(va.x * sc.x + sh.x, 0.f);
                va.y = fmaxf(va.y * sc.y + sh.y, 0.f);
                va.z = fmaxf(va.z * sc.z + sh.z, 0.f);
                va.w = fmaxf(va.w * sc.w + sh.w, 0.f);
            } else if (MODE == 2) {
                if (rootrow) {
                    va.x += rootrow[kg + 0]; va.y += rootrow[kg + 1];
                    va.z += rootrow[kg + 2]; va.w += rootrow[kg + 3];
                }
            }
        } else {
            va = make_float4(0.f, 0.f, 0.f, 0.f);
        }
    };
    auto split_sts = [&](int stage) {
        uint32_t h0, l0, h1, l1;
        int p0 = (kq * 2) * GP + lrow;
        int p1 = (kq * 2 + 1) * GP + lrow;
        split2(va.x, va.y, h0, l0);
        split2(va.z, va.w, h1, l1);
        sm[stage][0][p0] = h0; sm[stage][0][p1] = h1;
        sm[stage][1][p0] = l0; sm[stage][1][p1] = l1;
        split2(vb.x, vb.y, h0, l0);
        split2(vb.z, vb.w, h1, l1);
        sm[stage][2][p0] = h0; sm[stage][2][p1] = h1;
        sm[stage][3][p0] = l0; sm[stage][3][p1] = l1;
    };

    ldg(0);
    split_sts(0);
    __syncthreads();

    const int kl = lane & 3;
    const int rbase = wm * 32 + (lane >> 2);
    const int nbase = wn * 32 + (lane >> 2);

#pragma unroll 1
    for (int kt = 0; kt < 16; kt++) {
        const int cur = kt & 1;
        if (kt < 15) ldg(kt + 1);

        const uint32_t* Ah = sm[cur][0];
        const uint32_t* Al = sm[cur][1];
        const uint32_t* Bh = sm[cur][2];
        const uint32_t* Bl = sm[cur][3];

        uint32_t bh[4][2], bl[4][2];
#pragma unroll
        for (int nt = 0; nt < 4; nt++) {
            int n = nbase + nt * 8;
            bh[nt][0] = Bh[kl * GP + n];
            bh[nt][1] = Bh[(kl + 4) * GP + n];
            bl[nt][0] = Bl[kl * GP + n];
            bl[nt][1] = Bl[(kl + 4) * GP + n];
        }
#pragma unroll
        for (int mt = 0; mt < 2; mt++) {
            int r = rbase + mt * 16;
            uint32_t ah[4], al[4];
            ah[0] = Ah[kl * GP + r];
            ah[1] = Ah[kl * GP + r + 8];
            ah[2] = Ah[(kl + 4) * GP + r];
            ah[3] = Ah[(kl + 4) * GP + r + 8];
            al[0] = Al[kl * GP + r];
            al[1] = Al[kl * GP + r + 8];
            al[2] = Al[(kl + 4) * GP + r];
            al[3] = Al[(kl + 4) * GP + r + 8];
#pragma unroll
            for (int nt = 0; nt < 4; nt++) {
#define MMA(Af, Bf)                                                           \
    asm volatile(                                                             \
        "mma.sync.aligned.m16n8k16.row.col.f32.bf16.bf16.f32 "                \
        "{%0,%1,%2,%3}, {%4,%5,%6,%7}, {%8,%9}, {%0,%1,%2,%3};"               \
        : "+f"(acc[mt][nt][0]), "+f"(acc[mt][nt][1]),                         \
          "+f"(acc[mt][nt][2]), "+f"(acc[mt][nt][3])                          \
        : "r"(Af[0]), "r"(Af[1]), "r"(Af[2]), "r"(Af[3]),                     \
          "r"(Bf[0]), "r"(Bf[1]))
                MMA(al, bh[nt]);
                MMA(ah, bl[nt]);
                MMA(ah, bh[nt]);
#undef MMA
            }
        }

        if (kt < 15) {
            split_sts(cur ^ 1);
            __syncthreads();
        }
    }

    // ---- epilogue: bias add, store, fused column stats ----
#pragma unroll
    for (int nt = 0; nt < 4; nt++) {
        int cl = wn * 32 + nt * 8 + (lane & 3) * 2;   // block-local column
        int c = n0 + cl;
        float bv0 = bias[c], bv1 = bias[c + 1];
        float s0 = 0.f, s1 = 0.f, q0 = 0.f, q1 = 0.f;
#pragma unroll
        for (int mt = 0; mt < 2; mt++) {
            int r = m0 + wm * 32 + mt * 16 + (lane >> 2);
#pragma unroll
            for (int hh = 0; hh < 2; hh++) {
                int rr = r + hh * 8;
                if (rr < NN) {
                    float v0 = acc[mt][nt][hh * 2 + 0] + bv0;
                    float v1 = acc[mt][nt][hh * 2 + 1] + bv1;
                    *(float2*)(C + (size_t)rr * HD + c) = make_float2(v0, v1);
                    s0 += v0; s1 += v1;
                    q0 += v0 * v0; q1 += v1 * v1;
                }
            }
        }
#pragma unroll
        for (int o = 4; o < 32; o <<= 1) {
            s0 += __shfl_xor_sync(0xffffffffu, s0, o);
            s1 += __shfl_xor_sync(0xffffffffu, s1, o);
            q0 += __shfl_xor_sync(0xffffffffu, q0, o);
            q1 += __shfl_xor_sync(0xffffffffu, q1, o);
        }
        if ((lane >> 2) == 0) {
            atomicAdd(&s_sum[cl],     s0);
            atomicAdd(&s_sum[cl + 1], s1);
            atomicAdd(&s_ss[cl],      q0);
            atomicAdd(&s_ss[cl + 1],  q1);
        }
    }
    __syncthreads();
    if (tid < 128) {
        atomicAdd(&g_sum[n0 + tid],   (double)s_sum[tid]);
        atomicAdd(&g_sqsum[n0 + tid], (double)s_ss[tid]);
    }
}

// ---------------- residual + LayerNorm: h = LN(h + relu(y2*s+t)) ----------------
__global__ void k_resln(const float* __restrict__ y2,
                        const float* __restrict__ lng, const float* __restrict__ lnb) {
    int r = blockIdx.x;
    int t = threadIdx.x;
    size_t idx = (size_t)r * HD + t;
    float u = g_h[idx] + fmaxf(y2[idx] * g_scale[t] + g_shift[t], 0.f);

    float s = u, ss = u * u;
#pragma unroll
    for (int o = 16; o > 0; o >>= 1) {
        s  += __shfl_down_sync(0xffffffffu, s, o);
        ss += __shfl_down_sync(0xffffffffu, ss, o);
    }
    __shared__ float sh_s[8], sh_ss[8];
    int w = t >> 5, l = t & 31;
    if (l == 0) { sh_s[w] = s; sh_ss[w] = ss; }
    __syncthreads();
    float ts = 0.f, tss = 0.f;
#pragma unroll
    for (int i = 0; i < 8; i++) { ts += sh_s[i]; tss += sh_ss[i]; }

    float mean = ts * (1.f / HD);
    float var = tss * (1.f / HD) - mean * mean;
    if (var < 0.f) var = 0.f;
    float rs = rsqrtf(var + LN_EPS);
    g_h[idx] = lng[t] * (u - mean) * rs + lnb[t];
}

// ---------------- readout: out[g,o] = h[root_g] . Wout[o] ----------------
__global__ void k_out(const float* __restrict__ Wout, float* __restrict__ out) {
    int g = blockIdx.x;
    int w = threadIdx.x >> 5;
    int l = threadIdx.x & 31;
    const float* hr = g_h + (size_t)g * TREE_TOTAL * HD;
    const float* wr = Wout + (size_t)w * HD;
    float s = 0.f;
#pragma unroll
    for (int k = l; k < HD; k += 32) s += hr[k] * wr[k];
#pragma unroll
    for (int o = 16; o > 0; o >>= 1) s += __shfl_down_sync(0xffffffffu, s, o);
    if (l == 0) out[g * 32 + w] = s;
}

// ---------------- launch ----------------
extern "C" void kernel_launch(void* const* d_in, const int* in_sizes, int n_in,
                              void* d_out, int out_size) {
    const int*   x    = (const int*)d_in[0];
    const int*   esrc = (const int*)d_in[1];
    const int*   edst = (const int*)d_in[2];
    const float* ew   = (const float*)d_in[3];
    const float* en   = (const float*)d_in[6];
    const float* el   = (const float*)d_in[7];
    const float* W1   = (const float*)d_in[8];
    const float* b1   = (const float*)d_in[9];
    const float* g1   = (const float*)d_in[10];
    const float* be1  = (const float*)d_in[11];
    const float* W2   = (const float*)d_in[12];
    const float* b2   = (const float*)d_in[13];
    const float* g2   = (const float*)d_in[14];
    const float* be2  = (const float*)d_in[15];
    const float* lng  = (const float*)d_in[16];
    const float* lnb  = (const float*)d_in[17];
    const float* Wout = (const float*)d_in[18];
    float* out = (float*)d_out;

    float *h, *agg, *y1, *y2, *root;
    cudaGetSymbolAddress((void**)&h,    g_h);
    cudaGetSymbolAddress((void**)&agg,  g_agg);
    cudaGetSymbolAddress((void**)&y1,   g_y1);
    cudaGetSymbolAddress((void**)&y2,   g_y2);
    cudaGetSymbolAddress((void**)&root, g_root);

    dim3 ggrid(1024, 2);

    k_embed<<<(NN * 64) / 256, 256>>>(x, en, el);

    for (int i = 0; i < NL; i++) {
        const float* W1i = W1 + (size_t)i * HD * HD;
        const float* W2i = W2 + (size_t)i * HD * HD;
        const float* b1i = b1 + i * HD;
        const float* b2i = b2 + i * HD;
        const float* g1i = g1 + i * HD;
        const float* g2i = g2 + i * HD;
        const float* be1i = be1 + i * HD;
        const float* be2i = be2 + i * HD;
        const float* lngi = lng + i * HD;
        const float* lnbi = lnb + i * HD;

        if (i < NL - 1) {
            k_zero<<<(NN * 64) / 256, 256>>>((float4*)agg, NN * 64);
            k_scatter<<<(NE * 64) / 256, 256>>>(esrc, edst, ew);
            k_gemm_tc<0><<<ggrid, 512>>>(h, agg, W1i, b1i, y1);
        } else {
            k_zero<<<64, 256>>>((float4*)root, NG * HD / 4);
            k_rootsum<<<dim3(NG, 8), 256>>>();
            k_gemm_tc<2><<<ggrid, 512>>>(h, nullptr, W1i, b1i, y1);
        }
        k_makescale<<<1, 256>>>(g1i, be1i);
        k_gemm_tc<1><<<ggrid, 512>>>(y1, nullptr, W2i, b2i, y2);
        k_makescale<<<1, 256>>>(g2i, be2i);
        k_resln<<<NN, 256>>>(y2, lngi, lnbi);
    }

    k_out<<<NG, 1024>>>(Wout, out);
}

// round 7
// speedup vs baseline: 1.7795x; 1.1761x over previous
#include <cuda_runtime.h>
#include <math.h>
#include <stdint.h>

#define TREE_TOTAL 2047
#define NG 64
#define NN (NG * TREE_TOTAL)      // 131008
#define NE (2 * NN)               // 262016
#define HD 256
#define HALF 128
#define NL 4
#define BN_EPS 1e-5f
#define LN_EPS 1e-5f

// ---------------- scratch (no allocation allowed) ----------------
__device__ float  g_h  [(size_t)NN * HD];
__device__ float  g_agg[(size_t)NN * HD];
__device__ float  g_y1 [(size_t)NN * HD];
__device__ float  g_y2 [(size_t)NN * HD];
__device__ float  g_root[NG * HD];
__device__ double g_sum [HD];     // zero-init; k_makescale re-zeroes after use
__device__ double g_sqsum[HD];
__device__ float  g_scale[HD];
__device__ float  g_shift[HD];

// ---------------- embedding: h = concat(emb_node[x0], emb_label[x1]) ----------------
__global__ void k_embed(const int* __restrict__ x,
                        const float* __restrict__ en,
                        const float* __restrict__ el) {
    int idx = blockIdx.x * blockDim.x + threadIdx.x;
    if (idx >= NN * 64) return;
    int n = idx >> 6, q = idx & 63;
    float4 v;
    if (q < 32) {
        int e = x[2 * n];
        v = ((const float4*)(en + (size_t)e * HALF))[q];
    } else {
        int e = x[2 * n + 1];
        v = ((const float4*)(el + (size_t)e * HALF))[q - 32];
    }
    ((float4*)(g_h + (size_t)n * HD))[q] = v;
}

// ---------------- zero a float buffer ----------------
__global__ void k_zero(float4* __restrict__ p, int n4) {
    int i = blockIdx.x * blockDim.x + threadIdx.x;
    if (i < n4) p[i] = make_float4(0.f, 0.f, 0.f, 0.f);
}

// ---------------- edge scatter: agg[dst] += h[src] * w (vector reduction) --------
__global__ void k_scatter(const int* __restrict__ src, const int* __restrict__ dst,
                          const float* __restrict__ w) {
    int idx = blockIdx.x * blockDim.x + threadIdx.x;
    if (idx >= NE * 64) return;
    int e = idx >> 6, q = idx & 63;
    int s = src[e], d = dst[e];
    float ww = w[e];
    float4 v = ((const float4*)(g_h + (size_t)s * HD))[q];
    float* a = g_agg + (size_t)d * HD + q * 4;
    asm volatile("red.global.add.v4.f32 [%0], {%1, %2, %3, %4};"
                 :: "l"(a), "f"(v.x * ww), "f"(v.y * ww),
                    "f"(v.z * ww), "f"(v.w * ww) : "memory");
}

// ---------------- last layer: per-graph sum of all node features ----------------
__global__ void k_rootsum() {
    int g = blockIdx.x;
    int c = blockIdx.y;
    int t = threadIdx.x;
    int r0 = c * 256;
    int r1 = r0 + 256; if (r1 > TREE_TOTAL) r1 = TREE_TOTAL;
    float s = 0.f;
    const float* base = g_h + ((size_t)g * TREE_TOTAL) * HD + t;
    for (int r = r0; r < r1; r++) s += base[(size_t)r * HD];
    atomicAdd(&g_root[g * HD + t], s);
}

// ---------------- BN -> per-column scale/shift; re-zero stats ----------------
__global__ void k_makescale(const float* __restrict__ gamma, const float* __restrict__ beta) {
    int t = threadIdx.x;
    double m = g_sum[t] / (double)NN;
    double v = g_sqsum[t] / (double)NN - m * m;
    if (v < 0.0) v = 0.0;
    double rs = 1.0 / sqrt(v + (double)BN_EPS);
    float sc = gamma[t] * (float)rs;
    g_scale[t] = sc;
    g_shift[t] = beta[t] - (float)m * sc;
    g_sum[t] = 0.0;
    g_sqsum[t] = 0.0;
}

// ============================================================================
// BF16x3 tensor-core GEMM (error-compensated, ~fp32 accuracy):
//   a = ah + al (both bf16), b = bh + bl; C ~= ah*bh + ah*bl + al*bh
// mma.sync.aligned.m16n8k16.row.col.f32.bf16.bf16.f32
// Block tile 128x128, BK=16, 512 threads (16 warps, 4m x 4n), warp tile 32x32.
// Double-buffered smem, one __syncthreads per K-tile.
// MMA issue order is TERM-MAJOR so consecutive MMAs never share an
// accumulator (kills the RAW stall chain seen in the round-5 profile).
// Fused column sum/sumsq stats in epilogue (smem reduce -> 1 f64 atomic/col).
// MODE 0: a = A1 + A2
// MODE 1: a = relu(A1 * g_scale[k] + g_shift[k])
// MODE 2: a = A1 + (row % 2047 == 0 ? g_root[row/2047] : 0)
// ============================================================================
#define GP 136   // smem row stride (u32): conflict-free frag LDS

// split two floats (even k, odd k) into hi/lo bf16x2 packed words
__device__ __forceinline__ void split2(float e, float o, uint32_t& hi, uint32_t& lo) {
    uint32_t h;
    asm("cvt.rn.bf16x2.f32 %0, %1, %2;" : "=r"(h) : "f"(o), "f"(e));
    float ef = __uint_as_float(h << 16);
    float of = __uint_as_float(h & 0xffff0000u);
    float re = e - ef;
    float ro = o - of;
    uint32_t l;
    asm("cvt.rn.bf16x2.f32 %0, %1, %2;" : "=r"(l) : "f"(ro), "f"(re));
    hi = h; lo = l;
}

template <int MODE>
__global__ void __launch_bounds__(512, 1)
k_gemm_tc(const float* __restrict__ A1, const float* __restrict__ A2,
          const float* __restrict__ W, const float* __restrict__ bias,
          float* __restrict__ C) {
    // [stage][matrix: 0=Ah 1=Al 2=Bh 3=Bl][kp*GP + row]
    __shared__ uint32_t sm[2][4][8 * GP];
    __shared__ float s_sum[128], s_ss[128];

    const int m0 = blockIdx.x * 128;
    const int n0 = blockIdx.y * 128;
    const int tid = threadIdx.x;
    const int lane = tid & 31;
    const int warp = tid >> 5;
    const int wm = warp & 3;        // 32-row slab
    const int wn = warp >> 2;       // 32-col slab

    // loader mapping: one float4 of A and of B per K-tile
    const int lrow = tid >> 2;      // 0..127
    const int kq   = tid & 3;       // float4 index within 16-wide k
    const int grow = m0 + lrow;
    const bool rok = grow < NN;
    const float* rootrow = nullptr;
    if (MODE == 2 && rok && (grow % TREE_TOTAL) == 0)
        rootrow = g_root + (grow / TREE_TOTAL) * HD;

    if (tid < 128) { s_sum[tid] = 0.f; s_ss[tid] = 0.f; }

    float acc[2][4][4];
#pragma unroll
    for (int i = 0; i < 2; i++)
#pragma unroll
        for (int j = 0; j < 4; j++)
#pragma unroll
            for (int q = 0; q < 4; q++) acc[i][j][q] = 0.f;

    float4 va, vb;

    auto ldg = [&](int kt) {
        int kg = kt * 16 + kq * 4;
        vb = *(const float4*)(W + (size_t)(n0 + lrow) * HD + kg);
        if (rok) {
            va = *(const float4*)(A1 + (size_t)grow * HD + kg);
            if (MODE == 0) {
                float4 w4 = *(const float4*)(A2 + (size_t)grow * HD + kg);
                va.x += w4.x; va.y += w4.y; va.z += w4.z; va.w += w4.w;
            } else if (MODE == 1) {
                float4 sc = *(const float4*)(g_scale + kg);
                float4 sh = *(const float4*)(g_shift + kg);
                va.x = fmaxf(va.x * sc.x + sh.x, 0.f);
                va.y = fmaxf(va.y * sc.y + sh.y, 0.f);
                va.z = fmaxf(va.z * sc.z + sh.z, 0.f);
                va.w = fmaxf(va.w * sc.w + sh.w, 0.f);
            } else if (MODE == 2) {
                if (rootrow) {
                    va.x += rootrow[kg + 0]; va.y += rootrow[kg + 1];
                    va.z += rootrow[kg + 2]; va.w += rootrow[kg + 3];
                }
            }
        } else {
            va = make_float4(0.f, 0.f, 0.f, 0.f);
        }
    };
    auto split_sts = [&](int stage) {
        uint32_t h0, l0, h1, l1;
        int p0 = (kq * 2) * GP + lrow;
        int p1 = (kq * 2 + 1) * GP + lrow;
        split2(va.x, va.y, h0, l0);
        split2(va.z, va.w, h1, l1);
        sm[stage][0][p0] = h0; sm[stage][0][p1] = h1;
        sm[stage][1][p0] = l0; sm[stage][1][p1] = l1;
        split2(vb.x, vb.y, h0, l0);
        split2(vb.z, vb.w, h1, l1);
        sm[stage][2][p0] = h0; sm[stage][2][p1] = h1;
        sm[stage][3][p0] = l0; sm[stage][3][p1] = l1;
    };

    ldg(0);
    split_sts(0);
    __syncthreads();

    const int kl = lane & 3;
    const int rbase = wm * 32 + (lane >> 2);
    const int nbase = wn * 32 + (lane >> 2);

#pragma unroll 1
    for (int kt = 0; kt < 16; kt++) {
        const int cur = kt & 1;
        if (kt < 15) ldg(kt + 1);

        const uint32_t* Ah = sm[cur][0];
        const uint32_t* Al = sm[cur][1];
        const uint32_t* Bh = sm[cur][2];
        const uint32_t* Bl = sm[cur][3];

        // ---- load ALL fragments for this K-tile ----
        uint32_t bh[4][2], bl[4][2], ah[2][4], al[2][4];
#pragma unroll
        for (int nt = 0; nt < 4; nt++) {
            int n = nbase + nt * 8;
            bh[nt][0] = Bh[kl * GP + n];
            bh[nt][1] = Bh[(kl + 4) * GP + n];
            bl[nt][0] = Bl[kl * GP + n];
            bl[nt][1] = Bl[(kl + 4) * GP + n];
        }
#pragma unroll
        for (int mt = 0; mt < 2; mt++) {
            int r = rbase + mt * 16;
            ah[mt][0] = Ah[kl * GP + r];
            ah[mt][1] = Ah[kl * GP + r + 8];
            ah[mt][2] = Ah[(kl + 4) * GP + r];
            ah[mt][3] = Ah[(kl + 4) * GP + r + 8];
            al[mt][0] = Al[kl * GP + r];
            al[mt][1] = Al[kl * GP + r + 8];
            al[mt][2] = Al[(kl + 4) * GP + r];
            al[mt][3] = Al[(kl + 4) * GP + r + 8];
        }

#define MMA(ACC, Af, Bf)                                                      \
    asm volatile(                                                             \
        "mma.sync.aligned.m16n8k16.row.col.f32.bf16.bf16.f32 "                \
        "{%0,%1,%2,%3}, {%4,%5,%6,%7}, {%8,%9}, {%0,%1,%2,%3};"               \
        : "+f"((ACC)[0]), "+f"((ACC)[1]), "+f"((ACC)[2]), "+f"((ACC)[3])      \
        : "r"((Af)[0]), "r"((Af)[1]), "r"((Af)[2]), "r"((Af)[3]),             \
          "r"((Bf)[0]), "r"((Bf)[1]))

        // ---- term-major issue: consecutive MMAs hit distinct accumulators ----
#pragma unroll
        for (int mt = 0; mt < 2; mt++)
#pragma unroll
            for (int nt = 0; nt < 4; nt++)
                MMA(acc[mt][nt], al[mt], bh[nt]);
#pragma unroll
        for (int mt = 0; mt < 2; mt++)
#pragma unroll
            for (int nt = 0; nt < 4; nt++)
                MMA(acc[mt][nt], ah[mt], bl[nt]);
#pragma unroll
        for (int mt = 0; mt < 2; mt++)
#pragma unroll
            for (int nt = 0; nt < 4; nt++)
                MMA(acc[mt][nt], ah[mt], bh[nt]);
#undef MMA

        if (kt < 15) {
            split_sts(cur ^ 1);
            __syncthreads();
        }
    }

    // ---- epilogue: bias add, store, fused column stats ----
#pragma unroll
    for (int nt = 0; nt < 4; nt++) {
        int cl = wn * 32 + nt * 8 + (lane & 3) * 2;   // block-local column
        int c = n0 + cl;
        float bv0 = bias[c], bv1 = bias[c + 1];
        float s0 = 0.f, s1 = 0.f, q0 = 0.f, q1 = 0.f;
#pragma unroll
        for (int mt = 0; mt < 2; mt++) {
            int r = m0 + wm * 32 + mt * 16 + (lane >> 2);
#pragma unroll
            for (int hh = 0; hh < 2; hh++) {
                int rr = r + hh * 8;
                if (rr < NN) {
                    float v0 = acc[mt][nt][hh * 2 + 0] + bv0;
                    float v1 = acc[mt][nt][hh * 2 + 1] + bv1;
                    *(float2*)(C + (size_t)rr * HD + c) = make_float2(v0, v1);
                    s0 += v0; s1 += v1;
                    q0 += v0 * v0; q1 += v1 * v1;
                }
            }
        }
#pragma unroll
        for (int o = 4; o < 32; o <<= 1) {
            s0 += __shfl_xor_sync(0xffffffffu, s0, o);
            s1 += __shfl_xor_sync(0xffffffffu, s1, o);
            q0 += __shfl_xor_sync(0xffffffffu, q0, o);
            q1 += __shfl_xor_sync(0xffffffffu, q1, o);
        }
        if ((lane >> 2) == 0) {
            atomicAdd(&s_sum[cl],     s0);
            atomicAdd(&s_sum[cl + 1], s1);
            atomicAdd(&s_ss[cl],      q0);
            atomicAdd(&s_ss[cl + 1],  q1);
        }
    }
    __syncthreads();
    if (tid < 128) {
        atomicAdd(&g_sum[n0 + tid],   (double)s_sum[tid]);
        atomicAdd(&g_sqsum[n0 + tid], (double)s_ss[tid]);
    }
}

// ---------------- residual + LayerNorm: h = LN(h + relu(y2*s+t)) ----------------
// one warp per row, 8 rows per 256-thread block
__global__ void k_resln(const float* __restrict__ y2,
                        const float* __restrict__ lng, const float* __restrict__ lnb) {
    const int w = threadIdx.x >> 5, l = threadIdx.x & 31;
    const int r = blockIdx.x * 8 + w;
    const float4* hrow = (const float4*)(g_h + (size_t)r * HD);
    const float4* yrow = (const float4*)(y2 + (size_t)r * HD);

    float4 u[2];
    float s = 0.f, ss = 0.f;
#pragma unroll
    for (int i = 0; i < 2; i++) {
        int c4 = l + i * 32;
        float4 hv = hrow[c4];
        float4 yv = yrow[c4];
        float4 sc = ((const float4*)g_scale)[c4];
        float4 sh = ((const float4*)g_shift)[c4];
        float4 uu;
        uu.x = hv.x + fmaxf(yv.x * sc.x + sh.x, 0.f);
        uu.y = hv.y + fmaxf(yv.y * sc.y + sh.y, 0.f);
        uu.z = hv.z + fmaxf(yv.z * sc.z + sh.z, 0.f);
        uu.w = hv.w + fmaxf(yv.w * sc.w + sh.w, 0.f);
        u[i] = uu;
        s  += uu.x + uu.y + uu.z + uu.w;
        ss += uu.x * uu.x + uu.y * uu.y + uu.z * uu.z + uu.w * uu.w;
    }
#pragma unroll
    for (int o = 16; o > 0; o >>= 1) {
        s  += __shfl_xor_sync(0xffffffffu, s, o);
        ss += __shfl_xor_sync(0xffffffffu, ss, o);
    }
    float mean = s * (1.f / HD);
    float var = ss * (1.f / HD) - mean * mean;
    if (var < 0.f) var = 0.f;
    float rs = rsqrtf(var + LN_EPS);

    float4* orow = (float4*)(g_h + (size_t)r * HD);
#pragma unroll
    for (int i = 0; i < 2; i++) {
        int c4 = l + i * 32;
        float4 gg = ((const float4*)lng)[c4];
        float4 bb = ((const float4*)lnb)[c4];
        float4 uu = u[i];
        float4 o4;
        o4.x = gg.x * (uu.x - mean) * rs + bb.x;
        o4.y = gg.y * (uu.y - mean) * rs + bb.y;
        o4.z = gg.z * (uu.z - mean) * rs + bb.z;
        o4.w = gg.w * (uu.w - mean) * rs + bb.w;
        orow[c4] = o4;
    }
}

// ---------------- readout: out[g,o] = h[root_g] . Wout[o] ----------------
__global__ void k_out(const float* __restrict__ Wout, float* __restrict__ out) {
    int g = blockIdx.x;
    int w = threadIdx.x >> 5;
    int l = threadIdx.x & 31;
    const float* hr = g_h + (size_t)g * TREE_TOTAL * HD;
    const float* wr = Wout + (size_t)w * HD;
    float s = 0.f;
#pragma unroll
    for (int k = l; k < HD; k += 32) s += hr[k] * wr[k];
#pragma unroll
    for (int o = 16; o > 0; o >>= 1) s += __shfl_down_sync(0xffffffffu, s, o);
    if (l == 0) out[g * 32 + w] = s;
}

// ---------------- launch ----------------
extern "C" void kernel_launch(void* const* d_in, const int* in_sizes, int n_in,
                              void* d_out, int out_size) {
    const int*   x    = (const int*)d_in[0];
    const int*   esrc = (const int*)d_in[1];
    const int*   edst = (const int*)d_in[2];
    const float* ew   = (const float*)d_in[3];
    const float* en   = (const float*)d_in[6];
    const float* el   = (const float*)d_in[7];
    const float* W1   = (const float*)d_in[8];
    const float* b1   = (const float*)d_in[9];
    const float* g1   = (const float*)d_in[10];
    const float* be1  = (const float*)d_in[11];
    const float* W2   = (const float*)d_in[12];
    const float* b2   = (const float*)d_in[13];
    const float* g2   = (const float*)d_in[14];
    const float* be2  = (const float*)d_in[15];
    const float* lng  = (const float*)d_in[16];
    const float* lnb  = (const float*)d_in[17];
    const float* Wout = (const float*)d_in[18];
    float* out = (float*)d_out;

    float *h, *agg, *y1, *y2, *root;
    cudaGetSymbolAddress((void**)&h,    g_h);
    cudaGetSymbolAddress((void**)&agg,  g_agg);
    cudaGetSymbolAddress((void**)&y1,   g_y1);
    cudaGetSymbolAddress((void**)&y2,   g_y2);
    cudaGetSymbolAddress((void**)&root, g_root);

    dim3 ggrid(1024, 2);

    k_embed<<<(NN * 64) / 256, 256>>>(x, en, el);

    for (int i = 0; i < NL; i++) {
        const float* W1i = W1 + (size_t)i * HD * HD;
        const float* W2i = W2 + (size_t)i * HD * HD;
        const float* b1i = b1 + i * HD;
        const float* b2i = b2 + i * HD;
        const float* g1i = g1 + i * HD;
        const float* g2i = g2 + i * HD;
        const float* be1i = be1 + i * HD;
        const float* be2i = be2 + i * HD;
        const float* lngi = lng + i * HD;
        const float* lnbi = lnb + i * HD;

        if (i < NL - 1) {
            k_zero<<<(NN * 64) / 256, 256>>>((float4*)agg, NN * 64);
            k_scatter<<<(NE * 64) / 256, 256>>>(esrc, edst, ew);
            k_gemm_tc<0><<<ggrid, 512>>>(h, agg, W1i, b1i, y1);
        } else {
            k_zero<<<64, 256>>>((float4*)root, NG * HD / 4);
            k_rootsum<<<dim3(NG, 8), 256>>>();
            k_gemm_tc<2><<<ggrid, 512>>>(h, nullptr, W1i, b1i, y1);
        }
        k_makescale<<<1, 256>>>(g1i, be1i);
        k_gemm_tc<1><<<ggrid, 512>>>(y1, nullptr, W2i, b2i, y2);
        k_makescale<<<1, 256>>>(g2i, be2i);
        k_resln<<<NN / 8, 256>>>(y2, lngi, lnbi);
    }

    k_out<<<NG, 1024>>>(Wout, out);
}

// round 10
// speedup vs baseline: 2.2412x; 1.2595x over previous
#include <cuda_runtime.h>
#include <math.h>
#include <stdint.h>

#define TREE_TOTAL 2047
#define NG 64
#define NN (NG * TREE_TOTAL)      // 131008
#define NE (2 * NN)               // 262016
#define HD 256
#define HALF 128
#define NL 4
#define BN_EPS 1e-5f
#define LN_EPS 1e-5f

// ---------------- scratch (no allocation allowed) ----------------
__device__ float  g_h  [(size_t)NN * HD];
__device__ float  g_agg[(size_t)NN * HD];
__device__ float  g_y1 [(size_t)NN * HD];
__device__ float  g_y2 [(size_t)NN * HD];
__device__ float  g_root[NG * HD];
__device__ double g_sum [HD];     // zero-init; k_makescale re-zeroes after use
__device__ double g_sqsum[HD];
__device__ float  g_scale[HD];
__device__ float  g_shift[HD];

// ---------------- embedding: h = concat(emb_node[x0], emb_label[x1]) ----------------
__global__ void k_embed(const int* __restrict__ x,
                        const float* __restrict__ en,
                        const float* __restrict__ el) {
    int idx = blockIdx.x * blockDim.x + threadIdx.x;
    if (idx >= NN * 64) return;
    int n = idx >> 6, q = idx & 63;
    float4 v;
    if (q < 32) {
        int e = x[2 * n];
        v = ((const float4*)(en + (size_t)e * HALF))[q];
    } else {
        int e = x[2 * n + 1];
        v = ((const float4*)(el + (size_t)e * HALF))[q - 32];
    }
    ((float4*)(g_h + (size_t)n * HD))[q] = v;
}

// ---------------- zero a float buffer ----------------
__global__ void k_zero(float4* __restrict__ p, int n4) {
    int i = blockIdx.x * blockDim.x + threadIdx.x;
    if (i < n4) p[i] = make_float4(0.f, 0.f, 0.f, 0.f);
}

// ---------------- edge scatter: agg[dst] += h[src] * w (vector reduction) --------
__global__ void k_scatter(const int* __restrict__ src, const int* __restrict__ dst,
                          const float* __restrict__ w) {
    int idx = blockIdx.x * blockDim.x + threadIdx.x;
    if (idx >= NE * 64) return;
    int e = idx >> 6, q = idx & 63;
    int s = src[e], d = dst[e];
    float ww = w[e];
    float4 v = ((const float4*)(g_h + (size_t)s * HD))[q];
    float* a = g_agg + (size_t)d * HD + q * 4;
    asm volatile("red.global.add.v4.f32 [%0], {%1, %2, %3, %4};"
                 :: "l"(a), "f"(v.x * ww), "f"(v.y * ww),
                    "f"(v.z * ww), "f"(v.w * ww) : "memory");
}

// ---------------- last layer: per-graph sum of all node features ----------------
__global__ void k_rootsum() {
    int g = blockIdx.x;
    int c = blockIdx.y;
    int t = threadIdx.x;
    int r0 = c * 256;
    int r1 = r0 + 256; if (r1 > TREE_TOTAL) r1 = TREE_TOTAL;
    float s = 0.f;
    const float* base = g_h + ((size_t)g * TREE_TOTAL) * HD + t;
    for (int r = r0; r < r1; r++) s += base[(size_t)r * HD];
    atomicAdd(&g_root[g * HD + t], s);
}

// ---------------- BN -> per-column scale/shift; re-zero stats ----------------
__global__ void k_makescale(const float* __restrict__ gamma, const float* __restrict__ beta) {
    int t = threadIdx.x;
    double m = g_sum[t] / (double)NN;
    double v = g_sqsum[t] / (double)NN - m * m;
    if (v < 0.0) v = 0.0;
    double rs = 1.0 / sqrt(v + (double)BN_EPS);
    float sc = gamma[t] * (float)rs;
    g_scale[t] = sc;
    g_shift[t] = beta[t] - (float)m * sc;
    g_sum[t] = 0.0;
    g_sqsum[t] = 0.0;
}

// ============================================================================
// BF16x3 tensor-core GEMM, FULL-WIDTH tiles: C[128,256] per CTA, grid = 1024.
//   a = ah + al (both bf16), b = bh + bl; C ~= ah*bh + ah*bl + al*bh
// mma.sync.aligned.m16n8k16.row.col.f32.bf16.bf16.f32
// 512 threads (16 warps, 4m x 4n), warp tile 32x64, BK=16, double-buffered.
// A is read exactly once per GEMM (no N-split re-read).
// 3-phase fragment scheme caps live fragment registers at 32.
// Fused column sum/sumsq stats in epilogue.
// MODE 0: a = A1 + A2
// MODE 1: a = relu(A1 * g_scale[k] + g_shift[k])
// MODE 2: a = A1 + (row % 2047 == 0 ? g_root[row/2047] : 0)
// ============================================================================
#define GPA 136            // A smem row stride (u32), mod 32 == 8
#define GPB 264            // B smem row stride (u32), mod 32 == 8
#define A_WORDS (8 * GPA)  // 1088
#define B_WORDS (8 * GPB)  // 2112
#define STAGE_WORDS (2 * A_WORDS + 2 * B_WORDS)   // 6400
#define STATS_OFF (2 * STAGE_WORDS)               // 12800 (u32 idx)
#define SMEM_WORDS (STATS_OFF + 512)
#define SMEM_BYTES (SMEM_WORDS * 4)               // 53248

// split two floats (even k, odd k) into hi/lo bf16x2 packed words
__device__ __forceinline__ void split2(float e, float o, uint32_t& hi, uint32_t& lo) {
    uint32_t h;
    asm("cvt.rn.bf16x2.f32 %0, %1, %2;" : "=r"(h) : "f"(o), "f"(e));
    float ef = __uint_as_float(h << 16);
    float of = __uint_as_float(h & 0xffff0000u);
    float re = e - ef;
    float ro = o - of;
    uint32_t l;
    asm("cvt.rn.bf16x2.f32 %0, %1, %2;" : "=r"(l) : "f"(ro), "f"(re));
    hi = h; lo = l;
}

template <int MODE>
__global__ void __launch_bounds__(512, 1)
k_gemm_tc(const float* __restrict__ A1, const float* __restrict__ A2,
          const float* __restrict__ W, const float* __restrict__ bias,
          float* __restrict__ C) {
    extern __shared__ uint32_t dyn[];
    float* s_sum = (float*)(dyn + STATS_OFF);
    float* s_ss  = (float*)(dyn + STATS_OFF + 256);

    const int m0 = blockIdx.x * 128;
    const int tid = threadIdx.x;
    const int lane = tid & 31;
    const int warp = tid >> 5;
    const int wm = warp & 3;        // 32-row slab
    const int wn = warp >> 2;       // 64-col slab

    // loader mapping: A -> 1 float4, B -> 2 float4 per K-tile
    const int a_row = tid >> 2;     // 0..127
    const int a_kq  = tid & 3;      // float4 within 16-wide k
    const int b_row = tid >> 1;     // 0..255
    const int b_half = tid & 1;     // which 2 float4s

    const int grow = m0 + a_row;
    const bool rok = grow < NN;
    const float* rootrow = nullptr;
    if (MODE == 2 && rok && (grow % TREE_TOTAL) == 0)
        rootrow = g_root + (grow / TREE_TOTAL) * HD;

    if (tid < 256) { s_sum[tid] = 0.f; s_ss[tid] = 0.f; }

    float acc[2][8][4];
#pragma unroll
    for (int i = 0; i < 2; i++)
#pragma unroll
        for (int j = 0; j < 8; j++)
#pragma unroll
            for (int q = 0; q < 4; q++) acc[i][j][q] = 0.f;

    float4 va, vb0, vb1;

    auto ldg = [&](int kt) {
        int kgb = kt * 16 + (b_half * 2) * 4;
        vb0 = *(const float4*)(W + (size_t)b_row * HD + kgb);
        vb1 = *(const float4*)(W + (size_t)b_row * HD + kgb + 4);
        int kg = kt * 16 + a_kq * 4;
        if (rok) {
            va = *(const float4*)(A1 + (size_t)grow * HD + kg);
            if (MODE == 0) {
                float4 w4 = *(const float4*)(A2 + (size_t)grow * HD + kg);
                va.x += w4.x; va.y += w4.y; va.z += w4.z; va.w += w4.w;
            } else if (MODE == 1) {
                float4 sc = *(const float4*)(g_scale + kg);
                float4 sh = *(const float4*)(g_shift + kg);
                va.x = fmaxf(va.x * sc.x + sh.x, 0.f);
                va.y = fmaxf(va.y * sc.y + sh.y, 0.f);
                va.z = fmaxf(va.z * sc.z + sh.z, 0.f);
                va.w = fmaxf(va.w * sc.w + sh.w, 0.f);
            } else if (MODE == 2) {
                if (rootrow) {
                    va.x += rootrow[kg + 0]; va.y += rootrow[kg + 1];
                    va.z += rootrow[kg + 2]; va.w += rootrow[kg + 3];
                }
            }
        } else {
            va = make_float4(0.f, 0.f, 0.f, 0.f);
        }
    };
    auto split_sts = [&](int stage) {
        uint32_t* AH = dyn + stage * STAGE_WORDS;
        uint32_t* AL = AH + A_WORDS;
        uint32_t* BH = AL + A_WORDS;
        uint32_t* BL = BH + B_WORDS;
        uint32_t h0, l0, h1, l1;
        // A
        {
            int p0 = (a_kq * 2) * GPA + a_row;
            int p1 = (a_kq * 2 + 1) * GPA + a_row;
            split2(va.x, va.y, h0, l0);
            split2(va.z, va.w, h1, l1);
            AH[p0] = h0; AH[p1] = h1;
            AL[p0] = l0; AL[p1] = l1;
        }
        // B (2 float4s)
        {
            int kq = b_half * 2;
            int p0 = (kq * 2) * GPB + b_row;
            int p1 = (kq * 2 + 1) * GPB + b_row;
            split2(vb0.x, vb0.y, h0, l0);
            split2(vb0.z, vb0.w, h1, l1);
            BH[p0] = h0; BH[p1] = h1;
            BL[p0] = l0; BL[p1] = l1;
            p0 += 2 * GPB; p1 += 2 * GPB;
            split2(vb1.x, vb1.y, h0, l0);
            split2(vb1.z, vb1.w, h1, l1);
            BH[p0] = h0; BH[p1] = h1;
            BL[p0] = l0; BL[p1] = l1;
        }
    };

    ldg(0);
    split_sts(0);
    __syncthreads();

    const int kl = lane & 3;
    const int rbase = wm * 32 + (lane >> 2);
    const int nbase = wn * 64 + (lane >> 2);

#define MMA(ACC, Af, Bf)                                                      \
    asm volatile(                                                             \
        "mma.sync.aligned.m16n8k16.row.col.f32.bf16.bf16.f32 "                \
        "{%0,%1,%2,%3}, {%4,%5,%6,%7}, {%8,%9}, {%0,%1,%2,%3};"               \
        : "+f"((ACC)[0]), "+f"((ACC)[1]), "+f"((ACC)[2]), "+f"((ACC)[3])      \
        : "r"((Af)[0]), "r"((Af)[1]), "r"((Af)[2]), "r"((Af)[3]),             \
          "r"((Bf)[0]), "r"((Bf)[1]))

#pragma unroll 1
    for (int kt = 0; kt < 16; kt++) {
        const int cur = kt & 1;
        if (kt < 15) ldg(kt + 1);

        const uint32_t* AH = dyn + cur * STAGE_WORDS;
        const uint32_t* AL = AH + A_WORDS;
        const uint32_t* BH = AL + A_WORDS;
        const uint32_t* BL = BH + B_WORDS;

        // phase 1: al . bh
        uint32_t fa[2][4], fb[8][2];
#pragma unroll
        for (int mt = 0; mt < 2; mt++) {
            int r = rbase + mt * 16;
            fa[mt][0] = AL[kl * GPA + r];
            fa[mt][1] = AL[kl * GPA + r + 8];
            fa[mt][2] = AL[(kl + 4) * GPA + r];
            fa[mt][3] = AL[(kl + 4) * GPA + r + 8];
        }
#pragma unroll
        for (int nt = 0; nt < 8; nt++) {
            int n = nbase + nt * 8;
            fb[nt][0] = BH[kl * GPB + n];
            fb[nt][1] = BH[(kl + 4) * GPB + n];
        }
#pragma unroll
        for (int mt = 0; mt < 2; mt++)
#pragma unroll
            for (int nt = 0; nt < 8; nt++)
                MMA(acc[mt][nt], fa[mt], fb[nt]);

        // phase 2: ah . bh
        uint32_t fa2[2][4];
#pragma unroll
        for (int mt = 0; mt < 2; mt++) {
            int r = rbase + mt * 16;
            fa2[mt][0] = AH[kl * GPA + r];
            fa2[mt][1] = AH[kl * GPA + r + 8];
            fa2[mt][2] = AH[(kl + 4) * GPA + r];
            fa2[mt][3] = AH[(kl + 4) * GPA + r + 8];
        }
#pragma unroll
        for (int mt = 0; mt < 2; mt++)
#pragma unroll
            for (int nt = 0; nt < 8; nt++)
                MMA(acc[mt][nt], fa2[mt], fb[nt]);

        // phase 3: ah . bl (overwrite fb)
#pragma unroll
        for (int nt = 0; nt < 8; nt++) {
            int n = nbase + nt * 8;
            fb[nt][0] = BL[kl * GPB + n];
            fb[nt][1] = BL[(kl + 4) * GPB + n];
        }
#pragma unroll
        for (int mt = 0; mt < 2; mt++)
#pragma unroll
            for (int nt = 0; nt < 8; nt++)
                MMA(acc[mt][nt], fa2[mt], fb[nt]);

        if (kt < 15) {
            split_sts(cur ^ 1);
            __syncthreads();
        }
    }
#undef MMA

    // ---- epilogue: bias add, store, fused column stats ----
#pragma unroll
    for (int nt = 0; nt < 8; nt++) {
        int c = wn * 64 + nt * 8 + (lane & 3) * 2;   // global column (n0 = 0)
        float bv0 = bias[c], bv1 = bias[c + 1];
        float s0 = 0.f, s1 = 0.f, q0 = 0.f, q1 = 0.f;
#pragma unroll
        for (int mt = 0; mt < 2; mt++) {
            int r = m0 + wm * 32 + mt * 16 + (lane >> 2);
#pragma unroll
            for (int hh = 0; hh < 2; hh++) {
                int rr = r + hh * 8;
                if (rr < NN) {
                    float v0 = acc[mt][nt][hh * 2 + 0] + bv0;
                    float v1 = acc[mt][nt][hh * 2 + 1] + bv1;
                    *(float2*)(C + (size_t)rr * HD + c) = make_float2(v0, v1);
                    s0 += v0; s1 += v1;
                    q0 += v0 * v0; q1 += v1 * v1;
                }
            }
        }
#pragma unroll
        for (int o = 4; o < 32; o <<= 1) {
            s0 += __shfl_xor_sync(0xffffffffu, s0, o);
            s1 += __shfl_xor_sync(0xffffffffu, s1, o);
            q0 += __shfl_xor_sync(0xffffffffu, q0, o);
            q1 += __shfl_xor_sync(0xffffffffu, q1, o);
        }
        if ((lane >> 2) == 0) {
            atomicAdd(&s_sum[c],     s0);
            atomicAdd(&s_sum[c + 1], s1);
            atomicAdd(&s_ss[c],      q0);
            atomicAdd(&s_ss[c + 1],  q1);
        }
    }
    __syncthreads();
    if (tid < 256) {
        atomicAdd(&g_sum[tid],   (double)s_sum[tid]);
        atomicAdd(&g_sqsum[tid], (double)s_ss[tid]);
    }
}

// ---------------- residual + LayerNorm: h = LN(h + relu(y2*s+t)) ----------------
// one warp per row, 8 rows per 256-thread block
__global__ void k_resln(const float* __restrict__ y2,
                        const float* __restrict__ lng, const float* __restrict__ lnb) {
    const int w = threadIdx.x >> 5, l = threadIdx.x & 31;
    const int r = blockIdx.x * 8 + w;
    const float4* hrow = (const float4*)(g_h + (size_t)r * HD);
    const float4* yrow = (const float4*)(y2 + (size_t)r * HD);

    float4 u[2];
    float s = 0.f, ss = 0.f;
#pragma unroll
    for (int i = 0; i < 2; i++) {
        int c4 = l + i * 32;
        float4 hv = hrow[c4];
        float4 yv = yrow[c4];
        float4 sc = ((const float4*)g_scale)[c4];
        float4 sh = ((const float4*)g_shift)[c4];
        float4 uu;
        uu.x = hv.x + fmaxf(yv.x * sc.x + sh.x, 0.f);
        uu.y = hv.y + fmaxf(yv.y * sc.y + sh.y, 0.f);
        uu.z = hv.z + fmaxf(yv.z * sc.z + sh.z, 0.f);
        uu.w = hv.w + fmaxf(yv.w * sc.w + sh.w, 0.f);
        u[i] = uu;
        s  += uu.x + uu.y + uu.z + uu.w;
        ss += uu.x * uu.x + uu.y * uu.y + uu.z * uu.z + uu.w * uu.w;
    }
#pragma unroll
    for (int o = 16; o > 0; o >>= 1) {
        s  += __shfl_xor_sync(0xffffffffu, s, o);
        ss += __shfl_xor_sync(0xffffffffu, ss, o);
    }
    float mean = s * (1.f / HD);
    float var = ss * (1.f / HD) - mean * mean;
    if (var < 0.f) var = 0.f;
    float rs = rsqrtf(var + LN_EPS);

    float4* orow = (float4*)(g_h + (size_t)r * HD);
#pragma unroll
    for (int i = 0; i < 2; i++) {
        int c4 = l + i * 32;
        float4 gg = ((const float4*)lng)[c4];
        float4 bb = ((const float4*)lnb)[c4];
        float4 uu = u[i];
        float4 o4;
        o4.x = gg.x * (uu.x - mean) * rs + bb.x;
        o4.y = gg.y * (uu.y - mean) * rs + bb.y;
        o4.z = gg.z * (uu.z - mean) * rs + bb.z;
        o4.w = gg.w * (uu.w - mean) * rs + bb.w;
        orow[c4] = o4;
    }
}

// ---------------- readout: out[g,o] = h[root_g] . Wout[o] ----------------
__global__ void k_out(const float* __restrict__ Wout, float* __restrict__ out) {
    int g = blockIdx.x;
    int w = threadIdx.x >> 5;
    int l = threadIdx.x & 31;
    const float* hr = g_h + (size_t)g * TREE_TOTAL * HD;
    const float* wr = Wout + (size_t)w * HD;
    float s = 0.f;
#pragma unroll
    for (int k = l; k < HD; k += 32) s += hr[k] * wr[k];
#pragma unroll
    for (int o = 16; o > 0; o >>= 1) s += __shfl_down_sync(0xffffffffu, s, o);
    if (l == 0) out[g * 32 + w] = s;
}

// ---------------- launch ----------------
extern "C" void kernel_launch(void* const* d_in, const int* in_sizes, int n_in,
                              void* d_out, int out_size) {
    const int*   x    = (const int*)d_in[0];
    const int*   esrc = (const int*)d_in[1];
    const int*   edst = (const int*)d_in[2];
    const float* ew   = (const float*)d_in[3];
    const float* en   = (const float*)d_in[6];
    const float* el   = (const float*)d_in[7];
    const float* W1   = (const float*)d_in[8];
    const float* b1   = (const float*)d_in[9];
    const float* g1   = (const float*)d_in[10];
    const float* be1  = (const float*)d_in[11];
    const float* W2   = (const float*)d_in[12];
    const float* b2   = (const float*)d_in[13];
    const float* g2   = (const float*)d_in[14];
    const float* be2  = (const float*)d_in[15];
    const float* lng  = (const float*)d_in[16];
    const float* lnb  = (const float*)d_in[17];
    const float* Wout = (const float*)d_in[18];
    float* out = (float*)d_out;

    float *h, *agg, *y1, *y2, *root;
    cudaGetSymbolAddress((void**)&h,    g_h);
    cudaGetSymbolAddress((void**)&agg,  g_agg);
    cudaGetSymbolAddress((void**)&y1,   g_y1);
    cudaGetSymbolAddress((void**)&y2,   g_y2);
    cudaGetSymbolAddress((void**)&root, g_root);

    cudaFuncSetAttribute(k_gemm_tc<0>, cudaFuncAttributeMaxDynamicSharedMemorySize, SMEM_BYTES);
    cudaFuncSetAttribute(k_gemm_tc<1>, cudaFuncAttributeMaxDynamicSharedMemorySize, SMEM_BYTES);
    cudaFuncSetAttribute(k_gemm_tc<2>, cudaFuncAttributeMaxDynamicSharedMemorySize, SMEM_BYTES);

    const int ggrid = (NN + 127) / 128;   // 1024

    k_embed<<<(NN * 64) / 256, 256>>>(x, en, el);

    for (int i = 0; i < NL; i++) {
        const float* W1i = W1 + (size_t)i * HD * HD;
        const float* W2i = W2 + (size_t)i * HD * HD;
        const float* b1i = b1 + i * HD;
        const float* b2i = b2 + i * HD;
        const float* g1i = g1 + i * HD;
        const float* g2i = g2 + i * HD;
        const float* be1i = be1 + i * HD;
        const float* be2i = be2 + i * HD;
        const float* lngi = lng + i * HD;
        const float* lnbi = lnb + i * HD;

        if (i < NL - 1) {
            k_zero<<<(NN * 64) / 256, 256>>>((float4*)agg, NN * 64);
            k_scatter<<<(NE * 64) / 256, 256>>>(esrc, edst, ew);
            k_gemm_tc<0><<<ggrid, 512, SMEM_BYTES>>>(h, agg, W1i, b1i, y1);
        } else {
            k_zero<<<64, 256>>>((float4*)root, NG * HD / 4);
            k_rootsum<<<dim3(NG, 8), 256>>>();
            k_gemm_tc<2><<<ggrid, 512, SMEM_BYTES>>>(h, nullptr, W1i, b1i, y1);
        }
        k_makescale<<<1, 256>>>(g1i, be1i);
        k_gemm_tc<1><<<ggrid, 512, SMEM_BYTES>>>(y1, nullptr, W2i, b2i, y2);
        k_makescale<<<1, 256>>>(g2i, be2i);
        k_resln<<<NN / 8, 256>>>(y2, lngi, lnbi);
    }

    k_out<<<NG, 1024>>>(Wout, out);
}

// round 11
// speedup vs baseline: 2.3006x; 1.0265x over previous
#include <cuda_runtime.h>
#include <math.h>
#include <stdint.h>

#define TREE_TOTAL 2047
#define NG 64
#define NN (NG * TREE_TOTAL)      // 131008
#define NE (2 * NN)               // 262016
#define HD 256
#define HALF 128
#define NL 4
#define BN_EPS 1e-5f
#define LN_EPS 1e-5f

// ---------------- scratch (no allocation allowed) ----------------
__device__ float  g_h  [(size_t)NN * HD];
__device__ float  g_agg[(size_t)NN * HD];
__device__ float  g_y1 [(size_t)NN * HD];
__device__ float  g_y2 [(size_t)NN * HD];
__device__ float  g_root[NG * HD];
__device__ double g_sum [HD];     // zero-init; k_makescale re-zeroes after use
__device__ double g_sqsum[HD];
__device__ float  g_scale[HD];
__device__ float  g_shift[HD];
// pre-split weights: 8 matrices (W1 x4, W2 x4), [mat][row][kpair] bf16x2 words
__device__ uint32_t g_Wh[8 * 256 * 128];
__device__ uint32_t g_Wl[8 * 256 * 128];

// split two floats (even k, odd k) into hi/lo bf16x2 packed words
__device__ __forceinline__ void split2(float e, float o, uint32_t& hi, uint32_t& lo) {
    uint32_t h;
    asm("cvt.rn.bf16x2.f32 %0, %1, %2;" : "=r"(h) : "f"(o), "f"(e));
    float ef = __uint_as_float(h << 16);
    float of = __uint_as_float(h & 0xffff0000u);
    float re = e - ef;
    float ro = o - of;
    uint32_t l;
    asm("cvt.rn.bf16x2.f32 %0, %1, %2;" : "=r"(l) : "f"(ro), "f"(re));
    hi = h; lo = l;
}

// ---------------- pre-split all weight matrices ----------------
__global__ void k_splitW(const float* __restrict__ W1, const float* __restrict__ W2) {
    int idx = blockIdx.x * blockDim.x + threadIdx.x;   // 8*256*128
    if (idx >= 8 * 256 * 128) return;
    int p = idx & 127;          // kpair
    int r = (idx >> 7) & 255;   // row (output-n)
    int m = idx >> 15;          // matrix 0..7
    const float* W = (m < 4) ? (W1 + (size_t)m * HD * HD)
                             : (W2 + (size_t)(m - 4) * HD * HD);
    float e = W[r * HD + 2 * p];
    float o = W[r * HD + 2 * p + 1];
    uint32_t h, l;
    split2(e, o, h, l);
    g_Wh[idx] = h;
    g_Wl[idx] = l;
}

// ---------------- embedding: h = concat(emb_node[x0], emb_label[x1]) ----------------
__global__ void k_embed(const int* __restrict__ x,
                        const float* __restrict__ en,
                        const float* __restrict__ el) {
    int idx = blockIdx.x * blockDim.x + threadIdx.x;
    if (idx >= NN * 64) return;
    int n = idx >> 6, q = idx & 63;
    float4 v;
    if (q < 32) {
        int e = x[2 * n];
        v = ((const float4*)(en + (size_t)e * HALF))[q];
    } else {
        int e = x[2 * n + 1];
        v = ((const float4*)(el + (size_t)e * HALF))[q - 32];
    }
    ((float4*)(g_h + (size_t)n * HD))[q] = v;
}

// ---------------- edge scatter: agg[dst] += h[src] * w (vector reduction) --------
__global__ void k_scatter(const int* __restrict__ src, const int* __restrict__ dst,
                          const float* __restrict__ w) {
    int idx = blockIdx.x * blockDim.x + threadIdx.x;
    if (idx >= NE * 64) return;
    int e = idx >> 6, q = idx & 63;
    int s = src[e], d = dst[e];
    float ww = w[e];
    float4 v = ((const float4*)(g_h + (size_t)s * HD))[q];
    float* a = g_agg + (size_t)d * HD + q * 4;
    asm volatile("red.global.add.v4.f32 [%0], {%1, %2, %3, %4};"
                 :: "l"(a), "f"(v.x * ww), "f"(v.y * ww),
                    "f"(v.z * ww), "f"(v.w * ww) : "memory");
}

// ---------------- last layer: per-graph sum of all node features ----------------
__global__ void k_rootsum() {
    int g = blockIdx.x;
    int c = blockIdx.y;
    int t = threadIdx.x;
    int r0 = c * 256;
    int r1 = r0 + 256; if (r1 > TREE_TOTAL) r1 = TREE_TOTAL;
    float s = 0.f;
    const float* base = g_h + ((size_t)g * TREE_TOTAL) * HD + t;
    for (int r = r0; r < r1; r++) s += base[(size_t)r * HD];
    atomicAdd(&g_root[g * HD + t], s);
}

// ---------------- BN -> per-column scale/shift; re-zero stats ----------------
__global__ void k_makescale(const float* __restrict__ gamma, const float* __restrict__ beta) {
    int t = threadIdx.x;
    double m = g_sum[t] / (double)NN;
    double v = g_sqsum[t] / (double)NN - m * m;
    if (v < 0.0) v = 0.0;
    double rs = 1.0 / sqrt(v + (double)BN_EPS);
    float sc = gamma[t] * (float)rs;
    g_scale[t] = sc;
    g_shift[t] = beta[t] - (float)m * sc;
    g_sum[t] = 0.0;
    g_sqsum[t] = 0.0;
}

// ============================================================================
// BF16x3 tensor-core GEMM, full-width tiles: C[128,256] per CTA, grid = 1024.
// B (weights) pre-split in global -> cp.async straight into smem (no regs).
// A transformed + split in registers (mode-dependent).
// 512 threads, 16 warps (4m x 4n), warp tile 32x64, BK=16, double-buffered.
// MODE 0: a = A1 + A2
// MODE 1: a = relu(A1 * g_scale[k] + g_shift[k])
// MODE 2: a = A1 + (row % 2047 == 0 ? g_root[row/2047] : 0)
// ============================================================================
#define GPA 136                     // A smem row stride (u32)
#define A_WORDS (8 * GPA)           // 1088 per matrix
#define BROW 12                     // B smem row stride (u32), 48B (16B aligned)
#define B_WORDS (256 * BROW)        // 3072 per matrix
#define STAGE_WORDS (2 * A_WORDS + 2 * B_WORDS)   // 8320
#define STATS_OFF (2 * STAGE_WORDS)               // 16640
#define SMEM_WORDS (STATS_OFF + 512)
#define SMEM_BYTES (SMEM_WORDS * 4)               // 68608

__device__ __forceinline__ void cp16(uint32_t saddr, const void* gptr) {
    asm volatile("cp.async.cg.shared.global [%0], [%1], 16;"
                 :: "r"(saddr), "l"(gptr) : "memory");
}

template <int MODE>
__global__ void __launch_bounds__(512, 1)
k_gemm_tc(const float* __restrict__ A1, const float* __restrict__ A2,
          const uint32_t* __restrict__ Wh, const uint32_t* __restrict__ Wl,
          const float* __restrict__ bias, float* __restrict__ C) {
    extern __shared__ uint32_t dyn[];
    float* s_sum = (float*)(dyn + STATS_OFF);
    float* s_ss  = (float*)(dyn + STATS_OFF + 256);
    const uint32_t smem_base = (uint32_t)__cvta_generic_to_shared(dyn);

    const int m0 = blockIdx.x * 128;
    const int tid = threadIdx.x;
    const int lane = tid & 31;
    const int warp = tid >> 5;
    const int wm = warp & 3;        // 32-row slab
    const int wn = warp >> 2;       // 64-col slab

    // A loader: 1 float4 per K-tile
    const int a_row = tid >> 2;     // 0..127
    const int a_kq  = tid & 3;      // float4 within 16-wide k
    // B loader: one 16B hi chunk + one 16B lo chunk per K-tile
    const int b_row = tid >> 1;     // 0..255
    const int b_c   = tid & 1;      // chunk within row (kpairs 0-3 / 4-7)

    const int grow = m0 + a_row;
    const bool rok = grow < NN;
    const float* rootrow = nullptr;
    if (MODE == 2 && rok && (grow % TREE_TOTAL) == 0)
        rootrow = g_root + (grow / TREE_TOTAL) * HD;

    if (tid < 256) { s_sum[tid] = 0.f; s_ss[tid] = 0.f; }

    float acc[2][8][4];
#pragma unroll
    for (int i = 0; i < 2; i++)
#pragma unroll
        for (int j = 0; j < 8; j++)
#pragma unroll
            for (int q = 0; q < 4; q++) acc[i][j][q] = 0.f;

    float4 va;

    auto ldgA = [&](int kt) {
        int kg = kt * 16 + a_kq * 4;
        if (rok) {
            va = *(const float4*)(A1 + (size_t)grow * HD + kg);
            if (MODE == 0) {
                float4 w4 = *(const float4*)(A2 + (size_t)grow * HD + kg);
                va.x += w4.x; va.y += w4.y; va.z += w4.z; va.w += w4.w;
            } else if (MODE == 1) {
                float4 sc = *(const float4*)(g_scale + kg);
                float4 sh = *(const float4*)(g_shift + kg);
                va.x = fmaxf(va.x * sc.x + sh.x, 0.f);
                va.y = fmaxf(va.y * sc.y + sh.y, 0.f);
                va.z = fmaxf(va.z * sc.z + sh.z, 0.f);
                va.w = fmaxf(va.w * sc.w + sh.w, 0.f);
            } else if (MODE == 2) {
                if (rootrow) {
                    va.x += rootrow[kg + 0]; va.y += rootrow[kg + 1];
                    va.z += rootrow[kg + 2]; va.w += rootrow[kg + 3];
                }
            }
        } else {
            va = make_float4(0.f, 0.f, 0.f, 0.f);
        }
    };
    auto cpB = [&](int kt, int stage) {
        int goff = b_row * 128 + kt * 8 + b_c * 4;       // u32 index in g_Wh/g_Wl
        uint32_t soff = (stage * STAGE_WORDS + 2 * A_WORDS
                         + b_row * BROW + b_c * 4) * 4;  // byte offset, BH region
        cp16(smem_base + soff, Wh + goff);
        cp16(smem_base + soff + B_WORDS * 4, Wl + goff); // BL region
    };
    auto stsA = [&](int stage) {
        uint32_t* AH = dyn + stage * STAGE_WORDS;
        uint32_t* AL = AH + A_WORDS;
        uint32_t h0, l0, h1, l1;
        int p0 = (a_kq * 2) * GPA + a_row;
        int p1 = (a_kq * 2 + 1) * GPA + a_row;
        split2(va.x, va.y, h0, l0);
        split2(va.z, va.w, h1, l1);
        AH[p0] = h0; AH[p1] = h1;
        AL[p0] = l0; AL[p1] = l1;
    };

    // prologue
    ldgA(0);
    cpB(0, 0);
    asm volatile("cp.async.commit_group;" ::: "memory");
    stsA(0);
    asm volatile("cp.async.wait_group 0;" ::: "memory");
    __syncthreads();

    const int kl = lane & 3;
    const int rbase = wm * 32 + (lane >> 2);
    const int nbase = wn * 64 + (lane >> 2);

#define MMA(ACC, Af, Bf)                                                      \
    asm volatile(                                                             \
        "mma.sync.aligned.m16n8k16.row.col.f32.bf16.bf16.f32 "                \
        "{%0,%1,%2,%3}, {%4,%5,%6,%7}, {%8,%9}, {%0,%1,%2,%3};"               \
        : "+f"((ACC)[0]), "+f"((ACC)[1]), "+f"((ACC)[2]), "+f"((ACC)[3])      \
        : "r"((Af)[0]), "r"((Af)[1]), "r"((Af)[2]), "r"((Af)[3]),             \
          "r"((Bf)[0]), "r"((Bf)[1]))

#pragma unroll 1
    for (int kt = 0; kt < 16; kt++) {
        const int cur = kt & 1;
        if (kt < 15) {
            ldgA(kt + 1);
            cpB(kt + 1, cur ^ 1);
            asm volatile("cp.async.commit_group;" ::: "memory");
        }

        const uint32_t* AH = dyn + cur * STAGE_WORDS;
        const uint32_t* AL = AH + A_WORDS;
        const uint32_t* BH = AL + A_WORDS;
        const uint32_t* BL = BH + B_WORDS;

        // phase 1: al . bh
        uint32_t fa[2][4], fb[8][2];
#pragma unroll
        for (int mt = 0; mt < 2; mt++) {
            int r = rbase + mt * 16;
            fa[mt][0] = AL[kl * GPA + r];
            fa[mt][1] = AL[kl * GPA + r + 8];
            fa[mt][2] = AL[(kl + 4) * GPA + r];
            fa[mt][3] = AL[(kl + 4) * GPA + r + 8];
        }
#pragma unroll
        for (int nt = 0; nt < 8; nt++) {
            int n = nbase + nt * 8;
            fb[nt][0] = BH[n * BROW + kl];
            fb[nt][1] = BH[n * BROW + kl + 4];
        }
#pragma unroll
        for (int mt = 0; mt < 2; mt++)
#pragma unroll
            for (int nt = 0; nt < 8; nt++)
                MMA(acc[mt][nt], fa[mt], fb[nt]);

        // phase 2: ah . bh
        uint32_t fa2[2][4];
#pragma unroll
        for (int mt = 0; mt < 2; mt++) {
            int r = rbase + mt * 16;
            fa2[mt][0] = AH[kl * GPA + r];
            fa2[mt][1] = AH[kl * GPA + r + 8];
            fa2[mt][2] = AH[(kl + 4) * GPA + r];
            fa2[mt][3] = AH[(kl + 4) * GPA + r + 8];
        }
#pragma unroll
        for (int mt = 0; mt < 2; mt++)
#pragma unroll
            for (int nt = 0; nt < 8; nt++)
                MMA(acc[mt][nt], fa2[mt], fb[nt]);

        // phase 3: ah . bl (overwrite fb)
#pragma unroll
        for (int nt = 0; nt < 8; nt++) {
            int n = nbase + nt * 8;
            fb[nt][0] = BL[n * BROW + kl];
            fb[nt][1] = BL[n * BROW + kl + 4];
        }
#pragma unroll
        for (int mt = 0; mt < 2; mt++)
#pragma unroll
            for (int nt = 0; nt < 8; nt++)
                MMA(acc[mt][nt], fa2[mt], fb[nt]);

        if (kt < 15) {
            stsA(cur ^ 1);
            asm volatile("cp.async.wait_group 0;" ::: "memory");
            __syncthreads();
        }
    }
#undef MMA

    // ---- epilogue: bias add, store, fused column stats ----
#pragma unroll
    for (int nt = 0; nt < 8; nt++) {
        int c = wn * 64 + nt * 8 + (lane & 3) * 2;
        float bv0 = bias[c], bv1 = bias[c + 1];
        float s0 = 0.f, s1 = 0.f, q0 = 0.f, q1 = 0.f;
#pragma unroll
        for (int mt = 0; mt < 2; mt++) {
            int r = m0 + wm * 32 + mt * 16 + (lane >> 2);
#pragma unroll
            for (int hh = 0; hh < 2; hh++) {
                int rr = r + hh * 8;
                if (rr < NN) {
                    float v0 = acc[mt][nt][hh * 2 + 0] + bv0;
                    float v1 = acc[mt][nt][hh * 2 + 1] + bv1;
                    *(float2*)(C + (size_t)rr * HD + c) = make_float2(v0, v1);
                    s0 += v0; s1 += v1;
                    q0 += v0 * v0; q1 += v1 * v1;
                }
            }
        }
#pragma unroll
        for (int o = 4; o < 32; o <<= 1) {
            s0 += __shfl_xor_sync(0xffffffffu, s0, o);
            s1 += __shfl_xor_sync(0xffffffffu, s1, o);
            q0 += __shfl_xor_sync(0xffffffffu, q0, o);
            q1 += __shfl_xor_sync(0xffffffffu, q1, o);
        }
        if ((lane >> 2) == 0) {
            atomicAdd(&s_sum[c],     s0);
            atomicAdd(&s_sum[c + 1], s1);
            atomicAdd(&s_ss[c],      q0);
            atomicAdd(&s_ss[c + 1],  q1);
        }
    }
    __syncthreads();
    if (tid < 256) {
        atomicAdd(&g_sum[tid],   (double)s_sum[tid]);
        atomicAdd(&g_sqsum[tid], (double)s_ss[tid]);
    }
}

// ---------------- residual + LayerNorm: h = LN(h + relu(y2*s+t)) ----------------
// one warp per row, 8 rows per 256-thread block
__global__ void k_resln(const float* __restrict__ y2,
                        const float* __restrict__ lng, const float* __restrict__ lnb) {
    const int w = threadIdx.x >> 5, l = threadIdx.x & 31;
    const int r = blockIdx.x * 8 + w;
    const float4* hrow = (const float4*)(g_h + (size_t)r * HD);
    const float4* yrow = (const float4*)(y2 + (size_t)r * HD);

    float4 u[2];
    float s = 0.f, ss = 0.f;
#pragma unroll
    for (int i = 0; i < 2; i++) {
        int c4 = l + i * 32;
        float4 hv = hrow[c4];
        float4 yv = yrow[c4];
        float4 sc = ((const float4*)g_scale)[c4];
        float4 sh = ((const float4*)g_shift)[c4];
        float4 uu;
        uu.x = hv.x + fmaxf(yv.x * sc.x + sh.x, 0.f);
        uu.y = hv.y + fmaxf(yv.y * sc.y + sh.y, 0.f);
        uu.z = hv.z + fmaxf(yv.z * sc.z + sh.z, 0.f);
        uu.w = hv.w + fmaxf(yv.w * sc.w + sh.w, 0.f);
        u[i] = uu;
        s  += uu.x + uu.y + uu.z + uu.w;
        ss += uu.x * uu.x + uu.y * uu.y + uu.z * uu.z + uu.w * uu.w;
    }
#pragma unroll
    for (int o = 16; o > 0; o >>= 1) {
        s  += __shfl_xor_sync(0xffffffffu, s, o);
        ss += __shfl_xor_sync(0xffffffffu, ss, o);
    }
    float mean = s * (1.f / HD);
    float var = ss * (1.f / HD) - mean * mean;
    if (var < 0.f) var = 0.f;
    float rs = rsqrtf(var + LN_EPS);

    float4* orow = (float4*)(g_h + (size_t)r * HD);
#pragma unroll
    for (int i = 0; i < 2; i++) {
        int c4 = l + i * 32;
        float4 gg = ((const float4*)lng)[c4];
        float4 bb = ((const float4*)lnb)[c4];
        float4 uu = u[i];
        float4 o4;
        o4.x = gg.x * (uu.x - mean) * rs + bb.x;
        o4.y = gg.y * (uu.y - mean) * rs + bb.y;
        o4.z = gg.z * (uu.z - mean) * rs + bb.z;
        o4.w = gg.w * (uu.w - mean) * rs + bb.w;
        orow[c4] = o4;
    }
}

// ---------------- readout: out[g,o] = h[root_g] . Wout[o] ----------------
__global__ void k_out(const float* __restrict__ Wout, float* __restrict__ out) {
    int g = blockIdx.x;
    int w = threadIdx.x >> 5;
    int l = threadIdx.x & 31;
    const float* hr = g_h + (size_t)g * TREE_TOTAL * HD;
    const float* wr = Wout + (size_t)w * HD;
    float s = 0.f;
#pragma unroll
    for (int k = l; k < HD; k += 32) s += hr[k] * wr[k];
#pragma unroll
    for (int o = 16; o > 0; o >>= 1) s += __shfl_down_sync(0xffffffffu, s, o);
    if (l == 0) out[g * 32 + w] = s;
}

// ---------------- launch ----------------
extern "C" void kernel_launch(void* const* d_in, const int* in_sizes, int n_in,
                              void* d_out, int out_size) {
    const int*   x    = (const int*)d_in[0];
    const int*   esrc = (const int*)d_in[1];
    const int*   edst = (const int*)d_in[2];
    const float* ew   = (const float*)d_in[3];
    const float* en   = (const float*)d_in[6];
    const float* el   = (const float*)d_in[7];
    const float* W1   = (const float*)d_in[8];
    const float* b1   = (const float*)d_in[9];
    const float* g1   = (const float*)d_in[10];
    const float* be1  = (const float*)d_in[11];
    const float* W2   = (const float*)d_in[12];
    const float* b2   = (const float*)d_in[13];
    const float* g2   = (const float*)d_in[14];
    const float* be2  = (const float*)d_in[15];
    const float* lng  = (const float*)d_in[16];
    const float* lnb  = (const float*)d_in[17];
    const float* Wout = (const float*)d_in[18];
    float* out = (float*)d_out;

    float *h, *agg, *y1, *y2, *root;
    uint32_t *Wh, *Wl;
    cudaGetSymbolAddress((void**)&h,    g_h);
    cudaGetSymbolAddress((void**)&agg,  g_agg);
    cudaGetSymbolAddress((void**)&y1,   g_y1);
    cudaGetSymbolAddress((void**)&y2,   g_y2);
    cudaGetSymbolAddress((void**)&root, g_root);
    cudaGetSymbolAddress((void**)&Wh,   g_Wh);
    cudaGetSymbolAddress((void**)&Wl,   g_Wl);

    cudaFuncSetAttribute(k_gemm_tc<0>, cudaFuncAttributeMaxDynamicSharedMemorySize, SMEM_BYTES);
    cudaFuncSetAttribute(k_gemm_tc<1>, cudaFuncAttributeMaxDynamicSharedMemorySize, SMEM_BYTES);
    cudaFuncSetAttribute(k_gemm_tc<2>, cudaFuncAttributeMaxDynamicSharedMemorySize, SMEM_BYTES);

    const int ggrid = (NN + 127) / 128;   // 1024

    k_splitW<<<(8 * 256 * 128) / 256, 256>>>(W1, W2);
    k_embed<<<(NN * 64) / 256, 256>>>(x, en, el);

    for (int i = 0; i < NL; i++) {
        const uint32_t* Wh1 = Wh + (size_t)i * 32768;
        const uint32_t* Wl1 = Wl + (size_t)i * 32768;
        const uint32_t* Wh2 = Wh + (size_t)(i + 4) * 32768;
        const uint32_t* Wl2 = Wl + (size_t)(i + 4) * 32768;
        const float* b1i = b1 + i * HD;
        const float* b2i = b2 + i * HD;
        const float* g1i = g1 + i * HD;
        const float* g2i = g2 + i * HD;
        const float* be1i = be1 + i * HD;
        const float* be2i = be2 + i * HD;
        const float* lngi = lng + i * HD;
        const float* lnbi = lnb + i * HD;

        if (i < NL - 1) {
            cudaMemsetAsync(agg, 0, (size_t)NN * HD * sizeof(float));
            k_scatter<<<(NE * 64) / 256, 256>>>(esrc, edst, ew);
            k_gemm_tc<0><<<ggrid, 512, SMEM_BYTES>>>(h, agg, Wh1, Wl1, b1i, y1);
        } else {
            cudaMemsetAsync(root, 0, (size_t)NG * HD * sizeof(float));
            k_rootsum<<<dim3(NG, 8), 256>>>();
            k_gemm_tc<2><<<ggrid, 512, SMEM_BYTES>>>(h, nullptr, Wh1, Wl1, b1i, y1);
        }
        k_makescale<<<1, 256>>>(g1i, be1i);
        k_gemm_tc<1><<<ggrid, 512, SMEM_BYTES>>>(y1, nullptr, Wh2, Wl2, b2i, y2);
        k_makescale<<<1, 256>>>(g2i, be2i);
        k_resln<<<NN / 8, 256>>>(y2, lngi, lnbi);
    }

    k_out<<<NG, 1024>>>(Wout, out);
}